// round 6
// baseline (speedup 1.0000x reference)
#include <cuda_runtime.h>
#include <cstdint>

// Shapes (fixed for this problem)
static constexpr int L    = 64;    // tokens per window (TP*W)
static constexpr int ED   = 256;   // embed dim
static constexpr int NWIN = 256;   // f * nW
static constexpr int KC   = 32;    // k-chunk for GEMM1
static constexpr int WPAD = 260;   // padded row stride for transposed Wp chunk
static constexpr int TPB  = 256;

// Scratch for per-window A = deg @ edge_bias  (256 * 64 * 64 floats = 4 MB)
__device__ float g_A[NWIN * L * L];

__device__ __forceinline__ unsigned long long pack2(float lo, float hi) {
    unsigned long long r;
    asm("mov.b64 %0, {%1, %2};" : "=l"(r) : "f"(lo), "f"(hi));
    return r;
}
__device__ __forceinline__ unsigned long long fma2(unsigned long long a,
                                                   unsigned long long b,
                                                   unsigned long long c) {
    unsigned long long d;
    asm("fma.rn.f32x2 %0, %1, %2, %3;" : "=l"(d) : "l"(a), "l"(b), "l"(c));
    return d;
}
__device__ __forceinline__ float lo32(unsigned long long v) {
    return __uint_as_float((unsigned)(v & 0xffffffffull));
}
__device__ __forceinline__ float hi32(unsigned long long v) {
    return __uint_as_float((unsigned)(v >> 32));
}

// ---------------------------------------------------------------------------
// Kernel A: A_w = deg_mat[w] @ edge_bias[w]   (256 windows, 64x64x64 each)
// ---------------------------------------------------------------------------
__global__ __launch_bounds__(TPB) void precompute_A_kernel(
    const float* __restrict__ deg, const float* __restrict__ eb)
{
    __shared__ float sD[L][L];
    __shared__ float sE[L][L + 1];
    const int w = blockIdx.x;
    const float* dw = deg + (size_t)w * L * L;
    const float* ew = eb + (size_t)w * L * L;
    for (int i = threadIdx.x; i < L * L; i += TPB) {
        sD[i >> 6][i & 63] = dw[i];
        sE[i >> 6][i & 63] = ew[i];
    }
    __syncthreads();
    const int tp = threadIdx.x >> 4;
    const int tq = threadIdx.x & 15;
    float acc[4][4];
    #pragma unroll
    for (int i = 0; i < 4; ++i)
        #pragma unroll
        for (int j = 0; j < 4; ++j) acc[i][j] = 0.0f;

    #pragma unroll 8
    for (int k = 0; k < L; ++k) {
        float a0 = sD[tp * 4 + 0][k];
        float a1 = sD[tp * 4 + 1][k];
        float a2 = sD[tp * 4 + 2][k];
        float a3 = sD[tp * 4 + 3][k];
        float b0 = sE[k][tq * 4 + 0];
        float b1 = sE[k][tq * 4 + 1];
        float b2 = sE[k][tq * 4 + 2];
        float b3 = sE[k][tq * 4 + 3];
        acc[0][0] += a0 * b0; acc[0][1] += a0 * b1; acc[0][2] += a0 * b2; acc[0][3] += a0 * b3;
        acc[1][0] += a1 * b0; acc[1][1] += a1 * b1; acc[1][2] += a1 * b2; acc[1][3] += a1 * b3;
        acc[2][0] += a2 * b0; acc[2][1] += a2 * b1; acc[2][2] += a2 * b2; acc[2][3] += a2 * b3;
        acc[3][0] += a3 * b0; acc[3][1] += a3 * b1; acc[3][2] += a3 * b2; acc[3][3] += a3 * b3;
    }
    float* Ao = g_A + (size_t)w * L * L;
    #pragma unroll
    for (int i = 0; i < 4; ++i)
        #pragma unroll
        for (int j = 0; j < 4; ++j)
            Ao[(tp * 4 + i) * L + (tq * 4 + j)] = acc[i][j];
}

// ---------------------------------------------------------------------------
// Kernel B: one block per window.
// Thread (warp tl, lane tj) owns rows tl*8..+7 and columns
// {4*tj..4*tj+3} U {128+4*tj..128+4*tj+3}  (conflict-free LDS.128 fragments)
// ---------------------------------------------------------------------------
__global__ __launch_bounds__(TPB, 2) void window_kernel(
    const float* __restrict__ x,
    const float* __restrict__ gamma,
    const float* __restrict__ beta,
    const float* __restrict__ Wp,
    const float* __restrict__ bp,
    float* __restrict__ out)
{
    extern __shared__ float smem[];
    float* sX = smem;                       // [L][ED]   64 KB (xn, later y)
    float* sW = smem + L * ED;              // [KC][WPAD] 33.3 KB (Wp^T chunk)
    float* sA = sW + KC * WPAD;             // [L][L]    16 KB

    const int n  = blockIdx.x;
    const int wi = n & 3;
    const int fi = (n >> 2) & 63;
    const int b  = n >> 8;
    const int w  = fi * 4 + wi;

    const size_t base = (((size_t)b * 256 + (size_t)fi * 4) * 64 + (size_t)wi * 16) * 256;
    const float* xbase = x + base;
    float*       obase = out + base;

    const int warp = threadIdx.x >> 5;
    const int lane = threadIdx.x & 31;

    // Load A_w into smem (only needed for GEMM2; covered by later barriers)
    const float* Aw = g_A + (size_t)w * L * L;
    #pragma unroll
    for (int i = threadIdx.x; i < L * L; i += TPB) sA[i] = Aw[i];

    // gamma/beta for this lane's fixed channel set
    float4 ga0 = *(const float4*)(gamma + lane * 4);
    float4 ga1 = *(const float4*)(gamma + 128 + lane * 4);
    float4 bt0 = *(const float4*)(beta  + lane * 4);
    float4 bt1 = *(const float4*)(beta  + 128 + lane * 4);

    // ---- LayerNorm: warp handles tokens warp*8 .. warp*8+7 ----
    #pragma unroll
    for (int t = 0; t < 8; ++t) {
        const int l = warp * 8 + t;
        const float* row = xbase + (((l >> 4) * 64 + (l & 15)) << 8);
        float4 v0 = *(const float4*)(row + lane * 4);
        float4 v1 = *(const float4*)(row + 128 + lane * 4);
        float s  = v0.x + v0.y + v0.z + v0.w + v1.x + v1.y + v1.z + v1.w;
        float s2 = v0.x * v0.x + v0.y * v0.y + v0.z * v0.z + v0.w * v0.w
                 + v1.x * v1.x + v1.y * v1.y + v1.z * v1.z + v1.w * v1.w;
        #pragma unroll
        for (int o = 16; o > 0; o >>= 1) {
            s  += __shfl_xor_sync(0xffffffffu, s,  o);
            s2 += __shfl_xor_sync(0xffffffffu, s2, o);
        }
        const float mu   = s * (1.0f / ED);
        const float var  = s2 * (1.0f / ED) - mu * mu;
        const float rstd = rsqrtf(var + 1e-5f);
        float4 o0, o1;
        o0.x = (v0.x - mu) * rstd * ga0.x + bt0.x;
        o0.y = (v0.y - mu) * rstd * ga0.y + bt0.y;
        o0.z = (v0.z - mu) * rstd * ga0.z + bt0.z;
        o0.w = (v0.w - mu) * rstd * ga0.w + bt0.w;
        o1.x = (v1.x - mu) * rstd * ga1.x + bt1.x;
        o1.y = (v1.y - mu) * rstd * ga1.y + bt1.y;
        o1.z = (v1.z - mu) * rstd * ga1.z + bt1.z;
        o1.w = (v1.w - mu) * rstd * ga1.w + bt1.w;
        *(float4*)(sX + l * ED + lane * 4)       = o0;
        *(float4*)(sX + l * ED + 128 + lane * 4) = o1;
    }
    __syncthreads();

    // ---- GEMM1: y[l][j] = sum_k xn[l][k] * Wp[j][k] + bp[j] ----
    const int tl = warp;
    const int tj = lane;
    // c[il][0..1] -> cols 4tj..4tj+3 ; c[il][2..3] -> cols 128+4tj..+3
    unsigned long long c[8][4];
    {
        float4 bb0 = *(const float4*)(bp + tj * 4);
        float4 bb1 = *(const float4*)(bp + 128 + tj * 4);
        unsigned long long q0 = pack2(bb0.x, bb0.y);
        unsigned long long q1 = pack2(bb0.z, bb0.w);
        unsigned long long q2 = pack2(bb1.x, bb1.y);
        unsigned long long q3 = pack2(bb1.z, bb1.w);
        #pragma unroll
        for (int il = 0; il < 8; ++il) {
            c[il][0] = q0; c[il][1] = q1; c[il][2] = q2; c[il][3] = q3;
        }
    }

    const float* sXrow = sX + tl * 8 * ED;   // this thread's 8 rows

    for (int k0 = 0; k0 < ED; k0 += KC) {
        // stage Wp chunk transposed: sW[kk][j] = Wp[j][k0+kk]
        // stores: column index = threadIdx.x -> lanes hit distinct banks
        #pragma unroll
        for (int it = 0; it < 8; ++it) {
            float4 v = *(const float4*)(Wp + (size_t)threadIdx.x * ED + k0 + it * 4);
            sW[(it * 4 + 0) * WPAD + threadIdx.x] = v.x;
            sW[(it * 4 + 1) * WPAD + threadIdx.x] = v.y;
            sW[(it * 4 + 2) * WPAD + threadIdx.x] = v.z;
            sW[(it * 4 + 3) * WPAD + threadIdx.x] = v.w;
        }
        __syncthreads();
        #pragma unroll 2
        for (int kk = 0; kk < KC; kk += 4) {
            // A: one broadcast LDS.128 per row covers 4 k-steps (1 wf each)
            float4 a4[8];
            #pragma unroll
            for (int il = 0; il < 8; ++il)
                a4[il] = *(const float4*)(sXrow + il * ED + k0 + kk);
            #pragma unroll
            for (int u = 0; u < 4; ++u) {
                const float* wr = sW + (kk + u) * WPAD;
                float4 b0 = *(const float4*)(wr + tj * 4);        // contiguous 512B
                float4 b1 = *(const float4*)(wr + 128 + tj * 4);  // contiguous 512B
                unsigned long long bq0 = pack2(b0.x, b0.y);
                unsigned long long bq1 = pack2(b0.z, b0.w);
                unsigned long long bq2 = pack2(b1.x, b1.y);
                unsigned long long bq3 = pack2(b1.z, b1.w);
                #pragma unroll
                for (int il = 0; il < 8; ++il) {
                    const float a = (u == 0) ? a4[il].x :
                                    (u == 1) ? a4[il].y :
                                    (u == 2) ? a4[il].z : a4[il].w;
                    unsigned long long aq = pack2(a, a);
                    c[il][0] = fma2(aq, bq0, c[il][0]);
                    c[il][1] = fma2(aq, bq1, c[il][1]);
                    c[il][2] = fma2(aq, bq2, c[il][2]);
                    c[il][3] = fma2(aq, bq3, c[il][3]);
                }
            }
        }
        __syncthreads();
    }

    // ---- stage y back into sX (xn dead); contiguous conflict-free stores ----
    #pragma unroll
    for (int il = 0; il < 8; ++il) {
        float* yr = sX + (tl * 8 + il) * ED;
        float4 o0 = make_float4(lo32(c[il][0]), hi32(c[il][0]),
                                lo32(c[il][1]), hi32(c[il][1]));
        float4 o1 = make_float4(lo32(c[il][2]), hi32(c[il][2]),
                                lo32(c[il][3]), hi32(c[il][3]));
        *(float4*)(yr + tj * 4)       = o0;
        *(float4*)(yr + 128 + tj * 4) = o1;
    }
    __syncthreads();

    // ---- GEMM2: z[p][j] = sum_q A[p][q] * y[q][j] ----
    #pragma unroll
    for (int il = 0; il < 8; ++il) {
        c[il][0] = 0ull; c[il][1] = 0ull; c[il][2] = 0ull; c[il][3] = 0ull;
    }
    const float* sArow = sA + tl * 8 * L;
    #pragma unroll 2
    for (int q = 0; q < L; q += 4) {
        float4 a4[8];
        #pragma unroll
        for (int il = 0; il < 8; ++il)
            a4[il] = *(const float4*)(sArow + il * L + q);
        #pragma unroll
        for (int u = 0; u < 4; ++u) {
            const float* yr = sX + (q + u) * ED;
            float4 b0 = *(const float4*)(yr + tj * 4);
            float4 b1 = *(const float4*)(yr + 128 + tj * 4);
            unsigned long long bq0 = pack2(b0.x, b0.y);
            unsigned long long bq1 = pack2(b0.z, b0.w);
            unsigned long long bq2 = pack2(b1.x, b1.y);
            unsigned long long bq3 = pack2(b1.z, b1.w);
            #pragma unroll
            for (int il = 0; il < 8; ++il) {
                const float a = (u == 0) ? a4[il].x :
                                (u == 1) ? a4[il].y :
                                (u == 2) ? a4[il].z : a4[il].w;
                unsigned long long aq = pack2(a, a);
                c[il][0] = fma2(aq, bq0, c[il][0]);
                c[il][1] = fma2(aq, bq1, c[il][1]);
                c[il][2] = fma2(aq, bq2, c[il][2]);
                c[il][3] = fma2(aq, bq3, c[il][3]);
            }
        }
    }

    // ---- windowed write-back (contiguous 512B per warp-row segment) ----
    #pragma unroll
    for (int il = 0; il < 8; ++il) {
        const int p = tl * 8 + il;
        float* orow = obase + (((p >> 4) * 64 + (p & 15)) << 8);
        float4 o0 = make_float4(lo32(c[il][0]), hi32(c[il][0]),
                                lo32(c[il][1]), hi32(c[il][1]));
        float4 o1 = make_float4(lo32(c[il][2]), hi32(c[il][2]),
                                lo32(c[il][3]), hi32(c[il][3]));
        *(float4*)(orow + tj * 4)       = o0;
        *(float4*)(orow + 128 + tj * 4) = o1;
    }
}

// ---------------------------------------------------------------------------
extern "C" void kernel_launch(void* const* d_in, const int* in_sizes, int n_in,
                              void* d_out, int out_size)
{
    (void)in_sizes; (void)n_in; (void)out_size;
    const float* x     = (const float*)d_in[0];
    const float* gamma = (const float*)d_in[1];
    const float* beta  = (const float*)d_in[2];
    const float* Wp    = (const float*)d_in[3];
    const float* bp    = (const float*)d_in[4];
    const float* eb    = (const float*)d_in[5];
    const float* deg   = (const float*)d_in[6];
    float* out = (float*)d_out;

    const size_t smem_bytes = (size_t)(L * ED + KC * WPAD + L * L) * sizeof(float); // 115200
    cudaFuncSetAttribute(window_kernel,
                         cudaFuncAttributeMaxDynamicSharedMemorySize,
                         (int)smem_bytes);

    precompute_A_kernel<<<NWIN, TPB>>>(deg, eb);
    window_kernel<<<2048, TPB, smem_bytes>>>(x, gamma, beta, Wp, bp, out);
}

// round 8
// speedup vs baseline: 1.5511x; 1.5511x over previous
#include <cuda_runtime.h>
#include <cuda_bf16.h>
#include <cstdint>

static constexpr int L    = 64;
static constexpr int ED   = 256;
static constexpr int NWIN = 256;
static constexpr int TPB  = 256;
static constexpr int KC   = 32;      // k-chunk for Wp staging

// smem strides (elements)
static constexpr int XS = 264;       // bf16 stride for xn / y rows (row = 528 B)
static constexpr int WS = 40;        // bf16 stride for Wp chunk rows (80 B)
static constexpr int AS = 72;        // bf16 stride for A_w rows (144 B)
static constexpr int ZS = 264;       // f32 stride for z staging (1056 B)

// smem offsets (bytes)
static constexpr int OFF_XH = 0;
static constexpr int OFF_XL = 64 * XS * 2;              // 33792
static constexpr int OFF_W  = OFF_XL + 64 * XS * 2;     // 67584
static constexpr int OFF_WH = OFF_W;
static constexpr int OFF_WL = OFF_W + 256 * WS * 2;     // +20480
static constexpr int OFF_AH = OFF_W;                    // aliases Wp chunk (phase-disjoint)
static constexpr int OFF_AL = OFF_W + 64 * AS * 2;      // +9216
static constexpr int OFF_Z  = 0;                        // aliases xn/y (phase-disjoint)
static constexpr int SMEM_TOTAL = OFF_W + 2 * 256 * WS * 2;   // 108544

// Pre-split bf16 hi/lo operand images
__device__ __nv_bfloat16 g_WpH[256 * 256];
__device__ __nv_bfloat16 g_WpL[256 * 256];
__device__ __nv_bfloat16 g_AH[NWIN * 64 * 64];
__device__ __nv_bfloat16 g_AL[NWIN * 64 * 64];

// ---------------------------------------------------------------- helpers
__device__ __forceinline__ uint32_t smem_u32(const void* p) {
    uint32_t a;
    asm("{ .reg .u64 t; cvta.to.shared.u64 t, %1; cvt.u32.u64 %0, t; }"
        : "=r"(a) : "l"(p));
    return a;
}
__device__ __forceinline__ void ldm4(uint32_t* r, uint32_t a) {
    asm volatile("ldmatrix.sync.aligned.m8n8.x4.shared.b16 {%0,%1,%2,%3}, [%4];"
                 : "=r"(r[0]), "=r"(r[1]), "=r"(r[2]), "=r"(r[3]) : "r"(a));
}
__device__ __forceinline__ void ldm4t(uint32_t* r, uint32_t a) {
    asm volatile("ldmatrix.sync.aligned.m8n8.x4.trans.shared.b16 {%0,%1,%2,%3}, [%4];"
                 : "=r"(r[0]), "=r"(r[1]), "=r"(r[2]), "=r"(r[3]) : "r"(a));
}
__device__ __forceinline__ void mma16816(float* d, const uint32_t* a,
                                         uint32_t b0, uint32_t b1) {
    asm volatile(
        "mma.sync.aligned.m16n8k16.row.col.f32.bf16.bf16.f32 "
        "{%0,%1,%2,%3}, {%4,%5,%6,%7}, {%8,%9}, {%0,%1,%2,%3};"
        : "+f"(d[0]), "+f"(d[1]), "+f"(d[2]), "+f"(d[3])
        : "r"(a[0]), "r"(a[1]), "r"(a[2]), "r"(a[3]), "r"(b0), "r"(b1));
}
__device__ __forceinline__ void split_bf16(float x, __nv_bfloat16& hi, __nv_bfloat16& lo) {
    hi = __float2bfloat16_rn(x);
    lo = __float2bfloat16_rn(x - __bfloat162float(hi));
}
__device__ __forceinline__ uint32_t pack_bf2(float a, float b) {
    __nv_bfloat162 v(__float2bfloat16_rn(a), __float2bfloat16_rn(b));
    return *(uint32_t*)&v;
}

// ---------------------------------------------------------------------------
// Prep: split Wp into bf16 hi/lo (row-major [j][k])
// ---------------------------------------------------------------------------
__global__ __launch_bounds__(TPB) void split_wp_kernel(const float* __restrict__ Wp) {
    int idx = blockIdx.x * TPB + threadIdx.x;     // 65536
    float v = Wp[idx];
    __nv_bfloat16 hi, lo; split_bf16(v, hi, lo);
    g_WpH[idx] = hi;
    g_WpL[idx] = lo;
}

// ---------------------------------------------------------------------------
// Prep: A_w = deg@eb (fp32), split to bf16 hi/lo (row-major [p][q])
// ---------------------------------------------------------------------------
__global__ __launch_bounds__(TPB) void precompute_A_kernel(
    const float* __restrict__ deg, const float* __restrict__ eb)
{
    __shared__ float sD[L][L];
    __shared__ float sE[L][L + 1];
    const int w = blockIdx.x;
    const float* dw = deg + (size_t)w * L * L;
    const float* ew = eb + (size_t)w * L * L;
    for (int i = threadIdx.x; i < L * L; i += TPB) {
        sD[i >> 6][i & 63] = dw[i];
        sE[i >> 6][i & 63] = ew[i];
    }
    __syncthreads();
    const int tp = threadIdx.x >> 4;
    const int tq = threadIdx.x & 15;
    float acc[4][4];
    #pragma unroll
    for (int i = 0; i < 4; ++i)
        #pragma unroll
        for (int j = 0; j < 4; ++j) acc[i][j] = 0.0f;
    #pragma unroll 8
    for (int k = 0; k < L; ++k) {
        float a0 = sD[tp * 4 + 0][k], a1 = sD[tp * 4 + 1][k];
        float a2 = sD[tp * 4 + 2][k], a3 = sD[tp * 4 + 3][k];
        float b0 = sE[k][tq * 4 + 0], b1 = sE[k][tq * 4 + 1];
        float b2 = sE[k][tq * 4 + 2], b3 = sE[k][tq * 4 + 3];
        acc[0][0] += a0 * b0; acc[0][1] += a0 * b1; acc[0][2] += a0 * b2; acc[0][3] += a0 * b3;
        acc[1][0] += a1 * b0; acc[1][1] += a1 * b1; acc[1][2] += a1 * b2; acc[1][3] += a1 * b3;
        acc[2][0] += a2 * b0; acc[2][1] += a2 * b1; acc[2][2] += a2 * b2; acc[2][3] += a2 * b3;
        acc[3][0] += a3 * b0; acc[3][1] += a3 * b1; acc[3][2] += a3 * b2; acc[3][3] += a3 * b3;
    }
    #pragma unroll
    for (int i = 0; i < 4; ++i)
        #pragma unroll
        for (int j = 0; j < 4; ++j) {
            int p = tp * 4 + i, q = tq * 4 + j;
            __nv_bfloat16 hi, lo; split_bf16(acc[i][j], hi, lo);
            g_AH[(size_t)w * 4096 + p * 64 + q] = hi;
            g_AL[(size_t)w * 4096 + p * 64 + q] = lo;
        }
}

// ---------------------------------------------------------------------------
// Main kernel: one block per window, HMMA (mma.sync bf16x3) for both GEMMs.
// Warp wid: m-rows (wid&3)*16..+15, n-cols (wid>>2)*128..+127.
// ---------------------------------------------------------------------------
__global__ __launch_bounds__(TPB, 2) void window_kernel(
    const float* __restrict__ x,
    const float* __restrict__ gamma,
    const float* __restrict__ beta,
    const float* __restrict__ bp,
    float* __restrict__ out)
{
    extern __shared__ char smem[];
    const uint32_t sb = smem_u32(smem);
    const int tid  = threadIdx.x;
    const int wid  = tid >> 5;
    const int lane = tid & 31;
    const int gid  = lane >> 2;       // 0..7
    const int tig  = lane & 3;        // 0..3

    const int n  = blockIdx.x;
    const int wi = n & 3;
    const int fi = (n >> 2) & 63;
    const int b  = n >> 8;
    const int w  = fi * 4 + wi;
    const size_t base =
        (((size_t)b * 256 + (size_t)fi * 4) * 64 + (size_t)wi * 16) * 256;
    const float* xbase = x + base;
    float*       obase = out + base;

    const int wm = (wid & 3) * 16;
    const int wn = (wid >> 2) * 128;

    // ldmatrix lane->address components
    const int aRow  = ((lane >> 3) & 1) * 8 + (lane & 7);  // A-type / trans-B q-row
    const int aKblk = (lane >> 4) * 8;                     // A-type k add / trans-B j add
    const int bRow  = (lane >> 4) * 8 + (lane & 7);        // B-type (G1) j-row
    const int bKblk = ((lane >> 3) & 1) * 8;               // B-type (G1) k add

    // ---- LayerNorm -> bf16 hi/lo into sXh/sXl ----
    {
        const float4 ga0 = *(const float4*)(gamma + lane * 8);
        const float4 ga1 = *(const float4*)(gamma + lane * 8 + 4);
        const float4 bt0 = *(const float4*)(beta  + lane * 8);
        const float4 bt1 = *(const float4*)(beta  + lane * 8 + 4);
        #pragma unroll
        for (int tt = 0; tt < 8; ++tt) {
            const int t = wid * 8 + tt;
            const float* row = xbase + (((t >> 4) * 64 + (t & 15)) << 8);
            float4 v0 = *(const float4*)(row + lane * 8);
            float4 v1 = *(const float4*)(row + lane * 8 + 4);
            float s  = v0.x + v0.y + v0.z + v0.w + v1.x + v1.y + v1.z + v1.w;
            float s2 = v0.x*v0.x + v0.y*v0.y + v0.z*v0.z + v0.w*v0.w
                     + v1.x*v1.x + v1.y*v1.y + v1.z*v1.z + v1.w*v1.w;
            #pragma unroll
            for (int o = 16; o > 0; o >>= 1) {
                s  += __shfl_xor_sync(0xffffffffu, s,  o);
                s2 += __shfl_xor_sync(0xffffffffu, s2, o);
            }
            const float mu   = s * (1.0f / ED);
            const float var  = s2 * (1.0f / ED) - mu * mu;
            const float rstd = rsqrtf(var + 1e-5f);
            float nv[8];
            nv[0] = (v0.x - mu) * rstd * ga0.x + bt0.x;
            nv[1] = (v0.y - mu) * rstd * ga0.y + bt0.y;
            nv[2] = (v0.z - mu) * rstd * ga0.z + bt0.z;
            nv[3] = (v0.w - mu) * rstd * ga0.w + bt0.w;
            nv[4] = (v1.x - mu) * rstd * ga1.x + bt1.x;
            nv[5] = (v1.y - mu) * rstd * ga1.y + bt1.y;
            nv[6] = (v1.z - mu) * rstd * ga1.z + bt1.z;
            nv[7] = (v1.w - mu) * rstd * ga1.w + bt1.w;
            uint32_t hh[4], ll[4];
            #pragma unroll
            for (int i2 = 0; i2 < 4; ++i2) {
                __nv_bfloat16 h0, l0, h1, l1;
                split_bf16(nv[2 * i2],     h0, l0);
                split_bf16(nv[2 * i2 + 1], h1, l1);
                __nv_bfloat162 vh(h0, h1), vl(l0, l1);
                hh[i2] = *(uint32_t*)&vh;
                ll[i2] = *(uint32_t*)&vl;
            }
            *(uint4*)(smem + OFF_XH + t * (XS * 2) + lane * 16) =
                make_uint4(hh[0], hh[1], hh[2], hh[3]);
            *(uint4*)(smem + OFF_XL + t * (XS * 2) + lane * 16) =
                make_uint4(ll[0], ll[1], ll[2], ll[3]);
        }
    }
    __syncthreads();

    // ---- GEMM1: y = xn @ Wp^T  (bf16x3 HMMA), K = 256 in chunks of KC ----
    float acc[16][4];
    #pragma unroll
    for (int t = 0; t < 16; ++t)
        #pragma unroll
        for (int i2 = 0; i2 < 4; ++i2) acc[t][i2] = 0.0f;

    for (int k0 = 0; k0 < ED; k0 += KC) {
        // stage Wp chunk: thread tid = row j, copies 32 k (64 B) per half
        {
            const uint4* sh = (const uint4*)(g_WpH + (size_t)tid * 256 + k0);
            const uint4* sl = (const uint4*)(g_WpL + (size_t)tid * 256 + k0);
            uint4* dh = (uint4*)(smem + OFF_WH + tid * (WS * 2));
            uint4* dl = (uint4*)(smem + OFF_WL + tid * (WS * 2));
            dh[0] = sh[0]; dh[1] = sh[1]; dh[2] = sh[2]; dh[3] = sh[3];
            dl[0] = sl[0]; dl[1] = sl[1]; dl[2] = sl[2]; dl[3] = sl[3];
        }
        __syncthreads();
        #pragma unroll
        for (int ks = 0; ks < KC; ks += 16) {
            uint32_t aH[4], aL[4];
            ldm4(aH, sb + OFF_XH + (wm + aRow) * (XS * 2) + (k0 + ks + aKblk) * 2);
            ldm4(aL, sb + OFF_XL + (wm + aRow) * (XS * 2) + (k0 + ks + aKblk) * 2);
            #pragma unroll
            for (int g = 0; g < 8; ++g) {
                const int j0 = wn + g * 16;
                uint32_t bh[4], bl[4];
                ldm4(bh, sb + OFF_WH + (j0 + bRow) * (WS * 2) + (ks + bKblk) * 2);
                ldm4(bl, sb + OFF_WL + (j0 + bRow) * (WS * 2) + (ks + bKblk) * 2);
                mma16816(acc[2 * g],     aH, bh[0], bh[1]);
                mma16816(acc[2 * g + 1], aH, bh[2], bh[3]);
                mma16816(acc[2 * g],     aH, bl[0], bl[1]);
                mma16816(acc[2 * g + 1], aH, bl[2], bl[3]);
                mma16816(acc[2 * g],     aL, bh[0], bh[1]);
                mma16816(acc[2 * g + 1], aL, bh[2], bh[3]);
            }
        }
        __syncthreads();
    }

    // ---- epilogue1: y = acc + bias -> split hi/lo over sXh/sXl (xn dead) ----
    #pragma unroll
    for (int t = 0; t < 16; ++t) {
        const int j = wn + t * 8 + 2 * tig;
        const float2 bb = *(const float2*)(bp + j);
        float y00 = acc[t][0] + bb.x, y01 = acc[t][1] + bb.y;   // row wm+gid
        float y10 = acc[t][2] + bb.x, y11 = acc[t][3] + bb.y;   // row wm+gid+8
        __nv_bfloat16 h0, l0, h1, l1;
        split_bf16(y00, h0, l0); split_bf16(y01, h1, l1);
        __nv_bfloat162 vh0(h0, h1), vl0(l0, l1);
        *(uint32_t*)(smem + OFF_XH + (wm + gid) * (XS * 2) + j * 2) = *(uint32_t*)&vh0;
        *(uint32_t*)(smem + OFF_XL + (wm + gid) * (XS * 2) + j * 2) = *(uint32_t*)&vl0;
        split_bf16(y10, h0, l0); split_bf16(y11, h1, l1);
        __nv_bfloat162 vh1(h0, h1), vl1(l0, l1);
        *(uint32_t*)(smem + OFF_XH + (wm + gid + 8) * (XS * 2) + j * 2) = *(uint32_t*)&vh1;
        *(uint32_t*)(smem + OFF_XL + (wm + gid + 8) * (XS * 2) + j * 2) = *(uint32_t*)&vl1;
    }
    // ---- stage A_w hi/lo into sW area (Wp chunk dead) ----
    {
        const int half = tid >> 7, r = (tid >> 1) & 63, seg = tid & 1;
        const __nv_bfloat16* srcA = (half ? g_AL : g_AH) + (size_t)w * 4096 + r * 64 + seg * 32;
        char* dstA = smem + (half ? OFF_AL : OFF_AH) + r * (AS * 2) + seg * 64;
        ((uint4*)dstA)[0] = ((const uint4*)srcA)[0];
        ((uint4*)dstA)[1] = ((const uint4*)srcA)[1];
        ((uint4*)dstA)[2] = ((const uint4*)srcA)[2];
        ((uint4*)dstA)[3] = ((const uint4*)srcA)[3];
    }
    __syncthreads();

    // ---- GEMM2: z = A_w @ y  (bf16x3 HMMA), K = 64; B via ldmatrix.trans ----
    #pragma unroll
    for (int t = 0; t < 16; ++t)
        #pragma unroll
        for (int i2 = 0; i2 < 4; ++i2) acc[t][i2] = 0.0f;

    #pragma unroll
    for (int ks = 0; ks < 64; ks += 16) {
        uint32_t aH[4], aL[4];
        ldm4(aH, sb + OFF_AH + (wm + aRow) * (AS * 2) + (ks + aKblk) * 2);
        ldm4(aL, sb + OFF_AL + (wm + aRow) * (AS * 2) + (ks + aKblk) * 2);
        #pragma unroll
        for (int g = 0; g < 8; ++g) {
            const int j0 = wn + g * 16;
            // trans tiles: q = ks + ((lane>>3)&1)*8 + (lane&7), j = j0 + (lane>>4)*8
            const uint32_t qoff = (uint32_t)((ks + aRow) * (XS * 2) + (j0 + aKblk) * 2);
            uint32_t bh[4], bl[4];
            ldm4t(bh, sb + OFF_XH + qoff);
            ldm4t(bl, sb + OFF_XL + qoff);
            mma16816(acc[2 * g],     aH, bh[0], bh[1]);
            mma16816(acc[2 * g + 1], aH, bh[2], bh[3]);
            mma16816(acc[2 * g],     aH, bl[0], bl[1]);
            mma16816(acc[2 * g + 1], aH, bl[2], bl[3]);
            mma16816(acc[2 * g],     aL, bh[0], bh[1]);
            mma16816(acc[2 * g + 1], aL, bh[2], bh[3]);
        }
    }
    __syncthreads();

    // ---- epilogue2: z -> sZ (f32, stride ZS) over sX area ----
    #pragma unroll
    for (int t = 0; t < 16; ++t) {
        const int j = wn + t * 8 + 2 * tig;
        *(float2*)(smem + OFF_Z + (wm + gid)     * (ZS * 4) + j * 4) =
            make_float2(acc[t][0], acc[t][1]);
        *(float2*)(smem + OFF_Z + (wm + gid + 8) * (ZS * 4) + j * 4) =
            make_float2(acc[t][2], acc[t][3]);
    }
    __syncthreads();

    // ---- coalesced windowed write-back: warp wid -> tokens wid*8..+7 ----
    #pragma unroll
    for (int tt = 0; tt < 8; ++tt) {
        const int p = wid * 8 + tt;
        const char* zrow = smem + OFF_Z + p * (ZS * 4);
        float* orow = obase + (((p >> 4) * 64 + (p & 15)) << 8);
        float4 v0 = *(const float4*)(zrow + lane * 32);
        float4 v1 = *(const float4*)(zrow + lane * 32 + 16);
        *(float4*)(orow + lane * 8)     = v0;
        *(float4*)(orow + lane * 8 + 4) = v1;
    }
}

// ---------------------------------------------------------------------------
extern "C" void kernel_launch(void* const* d_in, const int* in_sizes, int n_in,
                              void* d_out, int out_size)
{
    (void)in_sizes; (void)n_in; (void)out_size;
    const float* x     = (const float*)d_in[0];
    const float* gamma = (const float*)d_in[1];
    const float* beta  = (const float*)d_in[2];
    const float* Wp    = (const float*)d_in[3];
    const float* bp    = (const float*)d_in[4];
    const float* eb    = (const float*)d_in[5];
    const float* deg   = (const float*)d_in[6];
    float* out = (float*)d_out;

    cudaFuncSetAttribute(window_kernel,
                         cudaFuncAttributeMaxDynamicSharedMemorySize, SMEM_TOTAL);

    split_wp_kernel<<<256, TPB>>>(Wp);
    precompute_A_kernel<<<NWIN, TPB>>>(deg, eb);
    window_kernel<<<2048, TPB, SMEM_TOTAL>>>(x, gamma, beta, bp, out);
}

// round 9
// speedup vs baseline: 2.4086x; 1.5528x over previous
#include <cuda_runtime.h>
#include <cuda_fp16.h>
#include <cstdint>

static constexpr int L    = 64;
static constexpr int ED   = 256;
static constexpr int NWIN = 256;
static constexpr int TPB  = 256;
static constexpr int KC   = 64;      // k-chunk for Wp staging (hi only now)

// smem strides (elements)
static constexpr int XS = 264;       // fp16 stride for xn / y rows (528 B)
static constexpr int WS = 72;        // fp16 stride for Wp chunk rows (144 B)
static constexpr int AS = 72;        // fp16 stride for A_w rows (144 B)
static constexpr int ZS = 264;       // f32 stride for z staging

// smem offsets (bytes)
static constexpr int OFF_XH = 0;
static constexpr int OFF_XL = 64 * XS * 2;              // 33792
static constexpr int OFF_W  = OFF_XL + 64 * XS * 2;     // 67584
static constexpr int OFF_AH = OFF_W;                    // aliases Wp chunk (phase-disjoint)
static constexpr int OFF_Z  = 0;                        // aliases xn/y (phase-disjoint)
static constexpr int SMEM_TOTAL = OFF_W + 256 * WS * 2; // 104448

// Pre-converted fp16 operand images (hi only — these sides stay uncorrected)
__device__ __half g_WpH[256 * 256];
__device__ __half g_AH[NWIN * 64 * 64];

// ---------------------------------------------------------------- helpers
__device__ __forceinline__ uint32_t smem_u32(const void* p) {
    uint32_t a;
    asm("{ .reg .u64 t; cvta.to.shared.u64 t, %1; cvt.u32.u64 %0, t; }"
        : "=r"(a) : "l"(p));
    return a;
}
__device__ __forceinline__ void ldm4(uint32_t* r, uint32_t a) {
    asm volatile("ldmatrix.sync.aligned.m8n8.x4.shared.b16 {%0,%1,%2,%3}, [%4];"
                 : "=r"(r[0]), "=r"(r[1]), "=r"(r[2]), "=r"(r[3]) : "r"(a));
}
__device__ __forceinline__ void ldm4t(uint32_t* r, uint32_t a) {
    asm volatile("ldmatrix.sync.aligned.m8n8.x4.trans.shared.b16 {%0,%1,%2,%3}, [%4];"
                 : "=r"(r[0]), "=r"(r[1]), "=r"(r[2]), "=r"(r[3]) : "r"(a));
}
__device__ __forceinline__ void mma16816(float* d, const uint32_t* a,
                                         uint32_t b0, uint32_t b1) {
    asm volatile(
        "mma.sync.aligned.m16n8k16.row.col.f32.f16.f16.f32 "
        "{%0,%1,%2,%3}, {%4,%5,%6,%7}, {%8,%9}, {%0,%1,%2,%3};"
        : "+f"(d[0]), "+f"(d[1]), "+f"(d[2]), "+f"(d[3])
        : "r"(a[0]), "r"(a[1]), "r"(a[2]), "r"(a[3]), "r"(b0), "r"(b1));
}
__device__ __forceinline__ void split_f16(float x, __half& hi, __half& lo) {
    hi = __float2half_rn(x);
    lo = __float2half_rn(x - __half2float(hi));
}

// ---------------------------------------------------------------------------
// Prep: Wp -> fp16 (row-major [j][k]), hi only
// ---------------------------------------------------------------------------
__global__ __launch_bounds__(TPB) void split_wp_kernel(const float* __restrict__ Wp) {
    int idx = blockIdx.x * TPB + threadIdx.x;     // 65536
    g_WpH[idx] = __float2half_rn(Wp[idx]);
}

// ---------------------------------------------------------------------------
// Prep: A_w = deg@eb (fp32), -> fp16 hi (row-major [p][q])
// ---------------------------------------------------------------------------
__global__ __launch_bounds__(TPB) void precompute_A_kernel(
    const float* __restrict__ deg, const float* __restrict__ eb)
{
    __shared__ float sD[L][L];
    __shared__ float sE[L][L + 1];
    const int w = blockIdx.x;
    const float* dw = deg + (size_t)w * L * L;
    const float* ew = eb + (size_t)w * L * L;
    for (int i = threadIdx.x; i < L * L; i += TPB) {
        sD[i >> 6][i & 63] = dw[i];
        sE[i >> 6][i & 63] = ew[i];
    }
    __syncthreads();
    const int tp = threadIdx.x >> 4;
    const int tq = threadIdx.x & 15;
    float acc[4][4];
    #pragma unroll
    for (int i = 0; i < 4; ++i)
        #pragma unroll
        for (int j = 0; j < 4; ++j) acc[i][j] = 0.0f;
    #pragma unroll 8
    for (int k = 0; k < L; ++k) {
        float a0 = sD[tp * 4 + 0][k], a1 = sD[tp * 4 + 1][k];
        float a2 = sD[tp * 4 + 2][k], a3 = sD[tp * 4 + 3][k];
        float b0 = sE[k][tq * 4 + 0], b1 = sE[k][tq * 4 + 1];
        float b2 = sE[k][tq * 4 + 2], b3 = sE[k][tq * 4 + 3];
        acc[0][0] += a0 * b0; acc[0][1] += a0 * b1; acc[0][2] += a0 * b2; acc[0][3] += a0 * b3;
        acc[1][0] += a1 * b0; acc[1][1] += a1 * b1; acc[1][2] += a1 * b2; acc[1][3] += a1 * b3;
        acc[2][0] += a2 * b0; acc[2][1] += a2 * b1; acc[2][2] += a2 * b2; acc[2][3] += a2 * b3;
        acc[3][0] += a3 * b0; acc[3][1] += a3 * b1; acc[3][2] += a3 * b2; acc[3][3] += a3 * b3;
    }
    #pragma unroll
    for (int i = 0; i < 4; ++i)
        #pragma unroll
        for (int j = 0; j < 4; ++j) {
            int p = tp * 4 + i, q = tq * 4 + j;
            g_AH[(size_t)w * 4096 + p * 64 + q] = __float2half_rn(acc[i][j]);
        }
}

// ---------------------------------------------------------------------------
// Main kernel: one block per window, HMMA fp16x2 for both GEMMs.
// GEMM1: (xnH + xnL) @ WpH^T  (xn rounding corrected, Wp uncorrected)
// GEMM2: AH @ (yH + yL)       (y rounding corrected, A uncorrected)
// Warp wid: m-rows (wid&3)*16..+15, n-cols (wid>>2)*128..+127.
// ---------------------------------------------------------------------------
__global__ __launch_bounds__(TPB, 2) void window_kernel(
    const float* __restrict__ x,
    const float* __restrict__ gamma,
    const float* __restrict__ beta,
    const float* __restrict__ bp,
    float* __restrict__ out)
{
    extern __shared__ char smem[];
    const uint32_t sb = smem_u32(smem);
    const int tid  = threadIdx.x;
    const int wid  = tid >> 5;
    const int lane = tid & 31;
    const int gid  = lane >> 2;       // 0..7
    const int tig  = lane & 3;        // 0..3

    const int n  = blockIdx.x;
    const int wi = n & 3;
    const int fi = (n >> 2) & 63;
    const int b  = n >> 8;
    const int w  = fi * 4 + wi;
    const size_t base =
        (((size_t)b * 256 + (size_t)fi * 4) * 64 + (size_t)wi * 16) * 256;
    const float* xbase = x + base;
    float*       obase = out + base;

    const int wm = (wid & 3) * 16;
    const int wn = (wid >> 2) * 128;

    // ldmatrix lane->address components
    const int aRow  = ((lane >> 3) & 1) * 8 + (lane & 7);  // A-type / trans-B q-row
    const int aKblk = (lane >> 4) * 8;                     // A-type k add / trans-B j add
    const int bRow  = (lane >> 4) * 8 + (lane & 7);        // B-type (G1) j-row
    const int bKblk = ((lane >> 3) & 1) * 8;               // B-type (G1) k add

    // ---- LayerNorm -> fp16 hi/lo into sXh/sXl ----
    {
        const float4 ga0 = *(const float4*)(gamma + lane * 8);
        const float4 ga1 = *(const float4*)(gamma + lane * 8 + 4);
        const float4 bt0 = *(const float4*)(beta  + lane * 8);
        const float4 bt1 = *(const float4*)(beta  + lane * 8 + 4);
        #pragma unroll
        for (int tt = 0; tt < 8; ++tt) {
            const int t = wid * 8 + tt;
            const float* row = xbase + (((t >> 4) * 64 + (t & 15)) << 8);
            float4 v0 = *(const float4*)(row + lane * 8);
            float4 v1 = *(const float4*)(row + lane * 8 + 4);
            float s  = v0.x + v0.y + v0.z + v0.w + v1.x + v1.y + v1.z + v1.w;
            float s2 = v0.x*v0.x + v0.y*v0.y + v0.z*v0.z + v0.w*v0.w
                     + v1.x*v1.x + v1.y*v1.y + v1.z*v1.z + v1.w*v1.w;
            #pragma unroll
            for (int o = 16; o > 0; o >>= 1) {
                s  += __shfl_xor_sync(0xffffffffu, s,  o);
                s2 += __shfl_xor_sync(0xffffffffu, s2, o);
            }
            const float mu   = s * (1.0f / ED);
            const float var  = s2 * (1.0f / ED) - mu * mu;
            const float rstd = rsqrtf(var + 1e-5f);
            float nv[8];
            nv[0] = (v0.x - mu) * rstd * ga0.x + bt0.x;
            nv[1] = (v0.y - mu) * rstd * ga0.y + bt0.y;
            nv[2] = (v0.z - mu) * rstd * ga0.z + bt0.z;
            nv[3] = (v0.w - mu) * rstd * ga0.w + bt0.w;
            nv[4] = (v1.x - mu) * rstd * ga1.x + bt1.x;
            nv[5] = (v1.y - mu) * rstd * ga1.y + bt1.y;
            nv[6] = (v1.z - mu) * rstd * ga1.z + bt1.z;
            nv[7] = (v1.w - mu) * rstd * ga1.w + bt1.w;
            uint32_t hh[4], ll[4];
            #pragma unroll
            for (int i2 = 0; i2 < 4; ++i2) {
                __half h0, l0, h1, l1;
                split_f16(nv[2 * i2],     h0, l0);
                split_f16(nv[2 * i2 + 1], h1, l1);
                __half2 vh = __halves2half2(h0, h1);
                __half2 vl = __halves2half2(l0, l1);
                hh[i2] = *(uint32_t*)&vh;
                ll[i2] = *(uint32_t*)&vl;
            }
            *(uint4*)(smem + OFF_XH + t * (XS * 2) + lane * 16) =
                make_uint4(hh[0], hh[1], hh[2], hh[3]);
            *(uint4*)(smem + OFF_XL + t * (XS * 2) + lane * 16) =
                make_uint4(ll[0], ll[1], ll[2], ll[3]);
        }
    }
    __syncthreads();

    // ---- GEMM1: y = xn @ Wp^T  (fp16x2 HMMA), K = 256 in chunks of KC ----
    float acc[16][4];
    #pragma unroll
    for (int t = 0; t < 16; ++t)
        #pragma unroll
        for (int i2 = 0; i2 < 4; ++i2) acc[t][i2] = 0.0f;

    for (int k0 = 0; k0 < ED; k0 += KC) {
        // stage WpH chunk: thread tid = row j, copies 64 k (128 B)
        {
            const uint4* sh = (const uint4*)(g_WpH + (size_t)tid * 256 + k0);
            uint4* dh = (uint4*)(smem + OFF_W + tid * (WS * 2));
            #pragma unroll
            for (int q2 = 0; q2 < 8; ++q2) dh[q2] = sh[q2];
        }
        __syncthreads();
        #pragma unroll
        for (int ks = 0; ks < KC; ks += 16) {
            uint32_t aH[4], aL[4];
            ldm4(aH, sb + OFF_XH + (wm + aRow) * (XS * 2) + (k0 + ks + aKblk) * 2);
            ldm4(aL, sb + OFF_XL + (wm + aRow) * (XS * 2) + (k0 + ks + aKblk) * 2);
            #pragma unroll
            for (int g = 0; g < 8; ++g) {
                const int j0 = wn + g * 16;
                uint32_t bh[4];
                ldm4(bh, sb + OFF_W + (j0 + bRow) * (WS * 2) + (ks + bKblk) * 2);
                mma16816(acc[2 * g],     aH, bh[0], bh[1]);
                mma16816(acc[2 * g + 1], aH, bh[2], bh[3]);
                mma16816(acc[2 * g],     aL, bh[0], bh[1]);
                mma16816(acc[2 * g + 1], aL, bh[2], bh[3]);
            }
        }
        __syncthreads();
    }

    // ---- epilogue1: y = acc + bias -> split hi/lo over sXh/sXl (xn dead) ----
    #pragma unroll
    for (int t = 0; t < 16; ++t) {
        const int j = wn + t * 8 + 2 * tig;
        const float2 bb = *(const float2*)(bp + j);
        float y00 = acc[t][0] + bb.x, y01 = acc[t][1] + bb.y;   // row wm+gid
        float y10 = acc[t][2] + bb.x, y11 = acc[t][3] + bb.y;   // row wm+gid+8
        __half h0, l0, h1, l1;
        split_f16(y00, h0, l0); split_f16(y01, h1, l1);
        __half2 vh0 = __halves2half2(h0, h1), vl0 = __halves2half2(l0, l1);
        *(uint32_t*)(smem + OFF_XH + (wm + gid) * (XS * 2) + j * 2) = *(uint32_t*)&vh0;
        *(uint32_t*)(smem + OFF_XL + (wm + gid) * (XS * 2) + j * 2) = *(uint32_t*)&vl0;
        split_f16(y10, h0, l0); split_f16(y11, h1, l1);
        __half2 vh1 = __halves2half2(h0, h1), vl1 = __halves2half2(l0, l1);
        *(uint32_t*)(smem + OFF_XH + (wm + gid + 8) * (XS * 2) + j * 2) = *(uint32_t*)&vh1;
        *(uint32_t*)(smem + OFF_XL + (wm + gid + 8) * (XS * 2) + j * 2) = *(uint32_t*)&vl1;
    }
    // ---- stage A_w (hi) into sW area (Wp chunk dead) ----
    {
        const int r = tid >> 2, seg = tid & 3;     // row 0..63, 32B segment
        const __half* srcA = g_AH + (size_t)w * 4096 + r * 64 + seg * 16;
        char* dstA = smem + OFF_AH + r * (AS * 2) + seg * 32;
        ((uint4*)dstA)[0] = ((const uint4*)srcA)[0];
        ((uint4*)dstA)[1] = ((const uint4*)srcA)[1];
    }
    __syncthreads();

    // ---- GEMM2: z = A_w @ y  (fp16x2), K = 64; B via ldmatrix.trans ----
    #pragma unroll
    for (int t = 0; t < 16; ++t)
        #pragma unroll
        for (int i2 = 0; i2 < 4; ++i2) acc[t][i2] = 0.0f;

    #pragma unroll
    for (int ks = 0; ks < 64; ks += 16) {
        uint32_t aH[4];
        ldm4(aH, sb + OFF_AH + (wm + aRow) * (AS * 2) + (ks + aKblk) * 2);
        #pragma unroll
        for (int g = 0; g < 8; ++g) {
            const int j0 = wn + g * 16;
            // trans tiles: q = ks + ((lane>>3)&1)*8 + (lane&7), j = j0 + (lane>>4)*8
            const uint32_t qoff = (uint32_t)((ks + aRow) * (XS * 2) + (j0 + aKblk) * 2);
            uint32_t bh[4], bl[4];
            ldm4t(bh, sb + OFF_XH + qoff);
            ldm4t(bl, sb + OFF_XL + qoff);
            mma16816(acc[2 * g],     aH, bh[0], bh[1]);
            mma16816(acc[2 * g + 1], aH, bh[2], bh[3]);
            mma16816(acc[2 * g],     aH, bl[0], bl[1]);
            mma16816(acc[2 * g + 1], aH, bl[2], bl[3]);
        }
    }
    __syncthreads();

    // ---- epilogue2: z -> sZ (f32, stride ZS) over sX area ----
    #pragma unroll
    for (int t = 0; t < 16; ++t) {
        const int j = wn + t * 8 + 2 * tig;
        *(float2*)(smem + OFF_Z + (wm + gid)     * (ZS * 4) + j * 4) =
            make_float2(acc[t][0], acc[t][1]);
        *(float2*)(smem + OFF_Z + (wm + gid + 8) * (ZS * 4) + j * 4) =
            make_float2(acc[t][2], acc[t][3]);
    }
    __syncthreads();

    // ---- coalesced windowed write-back: warp wid -> tokens wid*8..+7 ----
    #pragma unroll
    for (int tt = 0; tt < 8; ++tt) {
        const int p = wid * 8 + tt;
        const char* zrow = smem + OFF_Z + p * (ZS * 4);
        float* orow = obase + (((p >> 4) * 64 + (p & 15)) << 8);
        float4 v0 = *(const float4*)(zrow + lane * 32);
        float4 v1 = *(const float4*)(zrow + lane * 32 + 16);
        *(float4*)(orow + lane * 8)     = v0;
        *(float4*)(orow + lane * 8 + 4) = v1;
    }
}

// ---------------------------------------------------------------------------
extern "C" void kernel_launch(void* const* d_in, const int* in_sizes, int n_in,
                              void* d_out, int out_size)
{
    (void)in_sizes; (void)n_in; (void)out_size;
    const float* x     = (const float*)d_in[0];
    const float* gamma = (const float*)d_in[1];
    const float* beta  = (const float*)d_in[2];
    const float* Wp    = (const float*)d_in[3];
    const float* bp    = (const float*)d_in[4];
    const float* eb    = (const float*)d_in[5];
    const float* deg   = (const float*)d_in[6];
    float* out = (float*)d_out;

    cudaFuncSetAttribute(window_kernel,
                         cudaFuncAttributeMaxDynamicSharedMemorySize, SMEM_TOTAL);

    split_wp_kernel<<<256, TPB>>>(Wp);
    precompute_A_kernel<<<NWIN, TPB>>>(deg, eb);
    window_kernel<<<2048, TPB, SMEM_TOTAL>>>(x, gamma, beta, bp, out);
}

// round 10
// speedup vs baseline: 2.8158x; 1.1691x over previous
#include <cuda_runtime.h>
#include <cuda_fp16.h>
#include <cstdint>

static constexpr int L    = 64;
static constexpr int ED   = 256;
static constexpr int NWIN = 256;
static constexpr int TPB  = 256;
static constexpr int KC   = 64;      // k-chunk for Wp staging

// smem strides (elements)
static constexpr int XS = 264;       // fp16 stride for xn / y rows (528 B)
static constexpr int WS = 72;        // fp16 stride for Wp chunk rows (144 B)
static constexpr int AS = 72;        // fp16 stride for A_w rows (144 B)
static constexpr int ZS = 264;       // f32 stride for z staging

// smem offsets (bytes)
static constexpr int OFF_XH = 0;                        // 64*XS*2 = 33792
static constexpr int OFF_W  = 64 * XS * 2;              // 33792
static constexpr int OFF_AH = OFF_W;                    // aliases Wp chunk (phase-disjoint)
static constexpr int OFF_Z  = 0;                        // aliases xn/y (phase-disjoint)
static constexpr int SMEM_TOTAL = OFF_W + 256 * WS * 2; // 70656

// Pre-converted fp16 operand images
__device__ __half g_WpH[256 * 256];
__device__ __half g_AH[NWIN * 64 * 64];

// ---------------------------------------------------------------- helpers
__device__ __forceinline__ uint32_t smem_u32(const void* p) {
    uint32_t a;
    asm("{ .reg .u64 t; cvta.to.shared.u64 t, %1; cvt.u32.u64 %0, t; }"
        : "=r"(a) : "l"(p));
    return a;
}
__device__ __forceinline__ void ldm4(uint32_t* r, uint32_t a) {
    asm volatile("ldmatrix.sync.aligned.m8n8.x4.shared.b16 {%0,%1,%2,%3}, [%4];"
                 : "=r"(r[0]), "=r"(r[1]), "=r"(r[2]), "=r"(r[3]) : "r"(a));
}
__device__ __forceinline__ void ldm4t(uint32_t* r, uint32_t a) {
    asm volatile("ldmatrix.sync.aligned.m8n8.x4.trans.shared.b16 {%0,%1,%2,%3}, [%4];"
                 : "=r"(r[0]), "=r"(r[1]), "=r"(r[2]), "=r"(r[3]) : "r"(a));
}
__device__ __forceinline__ void mma16816(float* d, const uint32_t* a,
                                         uint32_t b0, uint32_t b1) {
    asm volatile(
        "mma.sync.aligned.m16n8k16.row.col.f32.f16.f16.f32 "
        "{%0,%1,%2,%3}, {%4,%5,%6,%7}, {%8,%9}, {%0,%1,%2,%3};"
        : "+f"(d[0]), "+f"(d[1]), "+f"(d[2]), "+f"(d[3])
        : "r"(a[0]), "r"(a[1]), "r"(a[2]), "r"(a[3]), "r"(b0), "r"(b1));
}

// ---------------------------------------------------------------------------
// Prep: Wp -> fp16 (row-major [j][k])
// ---------------------------------------------------------------------------
__global__ __launch_bounds__(TPB) void split_wp_kernel(const float* __restrict__ Wp) {
    int idx = blockIdx.x * TPB + threadIdx.x;     // 65536
    g_WpH[idx] = __float2half_rn(Wp[idx]);
}

// ---------------------------------------------------------------------------
// Prep: A_w = deg@eb (fp32), -> fp16 (row-major [p][q])
// ---------------------------------------------------------------------------
__global__ __launch_bounds__(TPB) void precompute_A_kernel(
    const float* __restrict__ deg, const float* __restrict__ eb)
{
    __shared__ float sD[L][L];
    __shared__ float sE[L][L + 1];
    const int w = blockIdx.x;
    const float* dw = deg + (size_t)w * L * L;
    const float* ew = eb + (size_t)w * L * L;
    for (int i = threadIdx.x; i < L * L; i += TPB) {
        sD[i >> 6][i & 63] = dw[i];
        sE[i >> 6][i & 63] = ew[i];
    }
    __syncthreads();
    const int tp = threadIdx.x >> 4;
    const int tq = threadIdx.x & 15;
    float acc[4][4];
    #pragma unroll
    for (int i = 0; i < 4; ++i)
        #pragma unroll
        for (int j = 0; j < 4; ++j) acc[i][j] = 0.0f;
    #pragma unroll 8
    for (int k = 0; k < L; ++k) {
        float a0 = sD[tp * 4 + 0][k], a1 = sD[tp * 4 + 1][k];
        float a2 = sD[tp * 4 + 2][k], a3 = sD[tp * 4 + 3][k];
        float b0 = sE[k][tq * 4 + 0], b1 = sE[k][tq * 4 + 1];
        float b2 = sE[k][tq * 4 + 2], b3 = sE[k][tq * 4 + 3];
        acc[0][0] += a0 * b0; acc[0][1] += a0 * b1; acc[0][2] += a0 * b2; acc[0][3] += a0 * b3;
        acc[1][0] += a1 * b0; acc[1][1] += a1 * b1; acc[1][2] += a1 * b2; acc[1][3] += a1 * b3;
        acc[2][0] += a2 * b0; acc[2][1] += a2 * b1; acc[2][2] += a2 * b2; acc[2][3] += a2 * b3;
        acc[3][0] += a3 * b0; acc[3][1] += a3 * b1; acc[3][2] += a3 * b2; acc[3][3] += a3 * b3;
    }
    #pragma unroll
    for (int i = 0; i < 4; ++i)
        #pragma unroll
        for (int j = 0; j < 4; ++j) {
            int p = tp * 4 + i, q = tq * 4 + j;
            g_AH[(size_t)w * 4096 + p * 64 + q] = __float2half_rn(acc[i][j]);
        }
}

// ---------------------------------------------------------------------------
// Main kernel: one block per window, plain fp16 HMMA for both GEMMs.
// Warp wid: m-rows (wid&3)*16..+15, n-cols (wid>>2)*128..+127.
// ---------------------------------------------------------------------------
__global__ __launch_bounds__(TPB, 2) void window_kernel(
    const float* __restrict__ x,
    const float* __restrict__ gamma,
    const float* __restrict__ beta,
    const float* __restrict__ bp,
    float* __restrict__ out)
{
    extern __shared__ char smem[];
    const uint32_t sb = smem_u32(smem);
    const int tid  = threadIdx.x;
    const int wid  = tid >> 5;
    const int lane = tid & 31;
    const int gid  = lane >> 2;       // 0..7
    const int tig  = lane & 3;        // 0..3

    const int n  = blockIdx.x;
    const int wi = n & 3;
    const int fi = (n >> 2) & 63;
    const int b  = n >> 8;
    const int w  = fi * 4 + wi;
    const size_t base =
        (((size_t)b * 256 + (size_t)fi * 4) * 64 + (size_t)wi * 16) * 256;
    const float* xbase = x + base;
    float*       obase = out + base;

    const int wm = (wid & 3) * 16;
    const int wn = (wid >> 2) * 128;

    // ldmatrix lane->address components
    const int aRow  = ((lane >> 3) & 1) * 8 + (lane & 7);  // A-type / trans-B q-row
    const int aKblk = (lane >> 4) * 8;                     // A-type k add / trans-B j add
    const int bRow  = (lane >> 4) * 8 + (lane & 7);        // B-type (G1) j-row
    const int bKblk = ((lane >> 3) & 1) * 8;               // B-type (G1) k add

    // ---- LayerNorm -> fp16 into sXh ----
    {
        const float4 ga0 = *(const float4*)(gamma + lane * 8);
        const float4 ga1 = *(const float4*)(gamma + lane * 8 + 4);
        const float4 bt0 = *(const float4*)(beta  + lane * 8);
        const float4 bt1 = *(const float4*)(beta  + lane * 8 + 4);
        #pragma unroll
        for (int tt = 0; tt < 8; ++tt) {
            const int t = wid * 8 + tt;
            const float* row = xbase + (((t >> 4) * 64 + (t & 15)) << 8);
            float4 v0 = *(const float4*)(row + lane * 8);
            float4 v1 = *(const float4*)(row + lane * 8 + 4);
            float s  = v0.x + v0.y + v0.z + v0.w + v1.x + v1.y + v1.z + v1.w;
            float s2 = v0.x*v0.x + v0.y*v0.y + v0.z*v0.z + v0.w*v0.w
                     + v1.x*v1.x + v1.y*v1.y + v1.z*v1.z + v1.w*v1.w;
            #pragma unroll
            for (int o = 16; o > 0; o >>= 1) {
                s  += __shfl_xor_sync(0xffffffffu, s,  o);
                s2 += __shfl_xor_sync(0xffffffffu, s2, o);
            }
            const float mu   = s * (1.0f / ED);
            const float var  = s2 * (1.0f / ED) - mu * mu;
            const float rstd = rsqrtf(var + 1e-5f);
            float nv[8];
            nv[0] = (v0.x - mu) * rstd * ga0.x + bt0.x;
            nv[1] = (v0.y - mu) * rstd * ga0.y + bt0.y;
            nv[2] = (v0.z - mu) * rstd * ga0.z + bt0.z;
            nv[3] = (v0.w - mu) * rstd * ga0.w + bt0.w;
            nv[4] = (v1.x - mu) * rstd * ga1.x + bt1.x;
            nv[5] = (v1.y - mu) * rstd * ga1.y + bt1.y;
            nv[6] = (v1.z - mu) * rstd * ga1.z + bt1.z;
            nv[7] = (v1.w - mu) * rstd * ga1.w + bt1.w;
            uint32_t hh[4];
            #pragma unroll
            for (int i2 = 0; i2 < 4; ++i2) {
                __half2 vh = __halves2half2(__float2half_rn(nv[2 * i2]),
                                            __float2half_rn(nv[2 * i2 + 1]));
                hh[i2] = *(uint32_t*)&vh;
            }
            *(uint4*)(smem + OFF_XH + t * (XS * 2) + lane * 16) =
                make_uint4(hh[0], hh[1], hh[2], hh[3]);
        }
    }
    __syncthreads();

    // ---- GEMM1: y = xn @ Wp^T  (fp16 HMMA), K = 256 in chunks of KC ----
    float acc[16][4];
    #pragma unroll
    for (int t = 0; t < 16; ++t)
        #pragma unroll
        for (int i2 = 0; i2 < 4; ++i2) acc[t][i2] = 0.0f;

    for (int k0 = 0; k0 < ED; k0 += KC) {
        // stage WpH chunk: thread tid = row j, copies 64 k (128 B)
        {
            const uint4* sh = (const uint4*)(g_WpH + (size_t)tid * 256 + k0);
            uint4* dh = (uint4*)(smem + OFF_W + tid * (WS * 2));
            #pragma unroll
            for (int q2 = 0; q2 < 8; ++q2) dh[q2] = sh[q2];
        }
        __syncthreads();
        #pragma unroll
        for (int ks = 0; ks < KC; ks += 16) {
            uint32_t aH[4];
            ldm4(aH, sb + OFF_XH + (wm + aRow) * (XS * 2) + (k0 + ks + aKblk) * 2);
            #pragma unroll
            for (int g = 0; g < 8; ++g) {
                const int j0 = wn + g * 16;
                uint32_t bh[4];
                ldm4(bh, sb + OFF_W + (j0 + bRow) * (WS * 2) + (ks + bKblk) * 2);
                mma16816(acc[2 * g],     aH, bh[0], bh[1]);
                mma16816(acc[2 * g + 1], aH, bh[2], bh[3]);
            }
        }
        __syncthreads();
    }

    // ---- epilogue1: y = acc + bias -> fp16 into sXh (xn dead) ----
    #pragma unroll
    for (int t = 0; t < 16; ++t) {
        const int j = wn + t * 8 + 2 * tig;
        const float2 bb = *(const float2*)(bp + j);
        float y00 = acc[t][0] + bb.x, y01 = acc[t][1] + bb.y;   // row wm+gid
        float y10 = acc[t][2] + bb.x, y11 = acc[t][3] + bb.y;   // row wm+gid+8
        __half2 vh0 = __halves2half2(__float2half_rn(y00), __float2half_rn(y01));
        __half2 vh1 = __halves2half2(__float2half_rn(y10), __float2half_rn(y11));
        *(uint32_t*)(smem + OFF_XH + (wm + gid)     * (XS * 2) + j * 2) = *(uint32_t*)&vh0;
        *(uint32_t*)(smem + OFF_XH + (wm + gid + 8) * (XS * 2) + j * 2) = *(uint32_t*)&vh1;
    }
    // ---- stage A_w into sW area (Wp chunk dead) ----
    {
        const int r = tid >> 2, seg = tid & 3;     // row 0..63, 32B segment
        const __half* srcA = g_AH + (size_t)w * 4096 + r * 64 + seg * 16;
        char* dstA = smem + OFF_AH + r * (AS * 2) + seg * 32;
        ((uint4*)dstA)[0] = ((const uint4*)srcA)[0];
        ((uint4*)dstA)[1] = ((const uint4*)srcA)[1];
    }
    __syncthreads();

    // ---- GEMM2: z = A_w @ y  (fp16), K = 64; B via ldmatrix.trans ----
    #pragma unroll
    for (int t = 0; t < 16; ++t)
        #pragma unroll
        for (int i2 = 0; i2 < 4; ++i2) acc[t][i2] = 0.0f;

    #pragma unroll
    for (int ks = 0; ks < 64; ks += 16) {
        uint32_t aH[4];
        ldm4(aH, sb + OFF_AH + (wm + aRow) * (AS * 2) + (ks + aKblk) * 2);
        #pragma unroll
        for (int g = 0; g < 8; ++g) {
            const int j0 = wn + g * 16;
            // trans tiles: q = ks + ((lane>>3)&1)*8 + (lane&7), j = j0 + (lane>>4)*8
            const uint32_t qoff = (uint32_t)((ks + aRow) * (XS * 2) + (j0 + aKblk) * 2);
            uint32_t bh[4];
            ldm4t(bh, sb + OFF_XH + qoff);
            mma16816(acc[2 * g],     aH, bh[0], bh[1]);
            mma16816(acc[2 * g + 1], aH, bh[2], bh[3]);
        }
    }
    __syncthreads();

    // ---- epilogue2: z -> sZ (f32, stride ZS) over sX area ----
    #pragma unroll
    for (int t = 0; t < 16; ++t) {
        const int j = wn + t * 8 + 2 * tig;
        *(float2*)(smem + OFF_Z + (wm + gid)     * (ZS * 4) + j * 4) =
            make_float2(acc[t][0], acc[t][1]);
        *(float2*)(smem + OFF_Z + (wm + gid + 8) * (ZS * 4) + j * 4) =
            make_float2(acc[t][2], acc[t][3]);
    }
    __syncthreads();

    // ---- coalesced windowed write-back: warp wid -> tokens wid*8..+7 ----
    #pragma unroll
    for (int tt = 0; tt < 8; ++tt) {
        const int p = wid * 8 + tt;
        const char* zrow = smem + OFF_Z + p * (ZS * 4);
        float* orow = obase + (((p >> 4) * 64 + (p & 15)) << 8);
        float4 v0 = *(const float4*)(zrow + lane * 32);
        float4 v1 = *(const float4*)(zrow + lane * 32 + 16);
        *(float4*)(orow + lane * 8)     = v0;
        *(float4*)(orow + lane * 8 + 4) = v1;
    }
}

// ---------------------------------------------------------------------------
extern "C" void kernel_launch(void* const* d_in, const int* in_sizes, int n_in,
                              void* d_out, int out_size)
{
    (void)in_sizes; (void)n_in; (void)out_size;
    const float* x     = (const float*)d_in[0];
    const float* gamma = (const float*)d_in[1];
    const float* beta  = (const float*)d_in[2];
    const float* Wp    = (const float*)d_in[3];
    const float* bp    = (const float*)d_in[4];
    const float* eb    = (const float*)d_in[5];
    const float* deg   = (const float*)d_in[6];
    float* out = (float*)d_out;

    cudaFuncSetAttribute(window_kernel,
                         cudaFuncAttributeMaxDynamicSharedMemorySize, SMEM_TOTAL);

    split_wp_kernel<<<256, TPB>>>(Wp);
    precompute_A_kernel<<<NWIN, TPB>>>(deg, eb);
    window_kernel<<<2048, TPB, SMEM_TOTAL>>>(x, gamma, beta, bp, out);
}

// round 12
// speedup vs baseline: 3.5228x; 1.2511x over previous
#include <cuda_runtime.h>
#include <cuda_fp16.h>
#include <cstdint>

static constexpr int L    = 64;
static constexpr int ED   = 256;
static constexpr int NWIN = 256;
static constexpr int TPB  = 256;
static constexpr int KC   = 64;      // k-chunk for Wp staging

// smem strides (elements)
static constexpr int XS = 264;       // fp16 stride for xn / y rows (528 B)
static constexpr int WS = 72;        // fp16 stride for Wp chunk rows (144 B, 16B-aligned!)
static constexpr int AS = 72;        // fp16 stride for A_w rows (144 B)

// smem offsets (bytes)
static constexpr int OFF_XH = 0;                         // 64*528 = 33792
static constexpr int OFF_B0 = 33792;                     // chunk buf 0 (36864)
static constexpr int OFF_B1 = OFF_B0 + 256 * WS * 2;     // 70656
static constexpr int OFF_A  = OFF_B0;                    // A_w aliases B0 (B0 dead at c=3)
static constexpr int SMEM_TOTAL = OFF_B1 + 256 * WS * 2; // 107520 -> 2 CTAs/SM

// Pre-converted fp16 operand images
__device__ __half g_WpH[256 * 256];
__device__ __half g_AH[NWIN * 64 * 64];

// ---------------------------------------------------------------- helpers
__device__ __forceinline__ uint32_t smem_u32(const void* p) {
    uint32_t a;
    asm("{ .reg .u64 t; cvta.to.shared.u64 t, %1; cvt.u32.u64 %0, t; }"
        : "=r"(a) : "l"(p));
    return a;
}
__device__ __forceinline__ void cp16(uint32_t s, const void* g) {
    asm volatile(
        "{ .reg .u64 gg; cvta.to.global.u64 gg, %1;"
        "  cp.async.cg.shared.global [%0], [gg], 16; }"
        :: "r"(s), "l"(g) : "memory");
}
#define CP_COMMIT() asm volatile("cp.async.commit_group;" ::: "memory")
#define CP_WAIT0()  asm volatile("cp.async.wait_group 0;" ::: "memory")

__device__ __forceinline__ void ldm4(uint32_t* r, uint32_t a) {
    asm volatile("ldmatrix.sync.aligned.m8n8.x4.shared.b16 {%0,%1,%2,%3}, [%4];"
                 : "=r"(r[0]), "=r"(r[1]), "=r"(r[2]), "=r"(r[3]) : "r"(a));
}
__device__ __forceinline__ void ldm4t(uint32_t* r, uint32_t a) {
    asm volatile("ldmatrix.sync.aligned.m8n8.x4.trans.shared.b16 {%0,%1,%2,%3}, [%4];"
                 : "=r"(r[0]), "=r"(r[1]), "=r"(r[2]), "=r"(r[3]) : "r"(a));
}
__device__ __forceinline__ void mma16816(float* d, const uint32_t* a,
                                         uint32_t b0, uint32_t b1) {
    asm volatile(
        "mma.sync.aligned.m16n8k16.row.col.f32.f16.f16.f32 "
        "{%0,%1,%2,%3}, {%4,%5,%6,%7}, {%8,%9}, {%0,%1,%2,%3};"
        : "+f"(d[0]), "+f"(d[1]), "+f"(d[2]), "+f"(d[3])
        : "r"(a[0]), "r"(a[1]), "r"(a[2]), "r"(a[3]), "r"(b0), "r"(b1));
}

// ---------------------------------------------------------------------------
// Prep: Wp -> fp16 (row-major [j][k])
// ---------------------------------------------------------------------------
__global__ __launch_bounds__(TPB) void split_wp_kernel(const float* __restrict__ Wp) {
    int idx = blockIdx.x * TPB + threadIdx.x;     // 65536
    g_WpH[idx] = __float2half_rn(Wp[idx]);
}

// ---------------------------------------------------------------------------
// Prep: A_w = deg@eb (fp32), -> fp16 (row-major [p][q])
// ---------------------------------------------------------------------------
__global__ __launch_bounds__(TPB) void precompute_A_kernel(
    const float* __restrict__ deg, const float* __restrict__ eb)
{
    __shared__ float sD[L][L];
    __shared__ float sE[L][L + 1];
    const int w = blockIdx.x;
    const float* dw = deg + (size_t)w * L * L;
    const float* ew = eb + (size_t)w * L * L;
    for (int i = threadIdx.x; i < L * L; i += TPB) {
        sD[i >> 6][i & 63] = dw[i];
        sE[i >> 6][i & 63] = ew[i];
    }
    __syncthreads();
    const int tp = threadIdx.x >> 4;
    const int tq = threadIdx.x & 15;
    float acc[4][4];
    #pragma unroll
    for (int i = 0; i < 4; ++i)
        #pragma unroll
        for (int j = 0; j < 4; ++j) acc[i][j] = 0.0f;
    #pragma unroll 8
    for (int k = 0; k < L; ++k) {
        float a0 = sD[tp * 4 + 0][k], a1 = sD[tp * 4 + 1][k];
        float a2 = sD[tp * 4 + 2][k], a3 = sD[tp * 4 + 3][k];
        float b0 = sE[k][tq * 4 + 0], b1 = sE[k][tq * 4 + 1];
        float b2 = sE[k][tq * 4 + 2], b3 = sE[k][tq * 4 + 3];
        acc[0][0] += a0 * b0; acc[0][1] += a0 * b1; acc[0][2] += a0 * b2; acc[0][3] += a0 * b3;
        acc[1][0] += a1 * b0; acc[1][1] += a1 * b1; acc[1][2] += a1 * b2; acc[1][3] += a1 * b3;
        acc[2][0] += a2 * b0; acc[2][1] += a2 * b1; acc[2][2] += a2 * b2; acc[2][3] += a2 * b3;
        acc[3][0] += a3 * b0; acc[3][1] += a3 * b1; acc[3][2] += a3 * b2; acc[3][3] += a3 * b3;
    }
    #pragma unroll
    for (int i = 0; i < 4; ++i)
        #pragma unroll
        for (int j = 0; j < 4; ++j) {
            int p = tp * 4 + i, q = tq * 4 + j;
            g_AH[(size_t)w * 4096 + p * 64 + q] = __float2half_rn(acc[i][j]);
        }
}

// ---------------------------------------------------------------------------
// Main kernel: one block per window, fp16 HMMA, cp.async double-buffered Wp,
// direct accumulator->gmem write-back. 6 barriers total.
// Warp wid: m-rows (wid&3)*16..+15, n-cols (wid>>2)*128..+127.
// ---------------------------------------------------------------------------
__global__ __launch_bounds__(TPB, 2) void window_kernel(
    const float* __restrict__ x,
    const float* __restrict__ gamma,
    const float* __restrict__ beta,
    const float* __restrict__ bp,
    float* __restrict__ out)
{
    extern __shared__ char smem[];
    const uint32_t sb = smem_u32(smem);
    const int tid  = threadIdx.x;
    const int wid  = tid >> 5;
    const int lane = tid & 31;
    const int gid  = lane >> 2;       // 0..7
    const int tig  = lane & 3;        // 0..3

    const int n  = blockIdx.x;
    const int wi = n & 3;
    const int fi = (n >> 2) & 63;
    const int b  = n >> 8;
    const int w  = fi * 4 + wi;
    const size_t base =
        (((size_t)b * 256 + (size_t)fi * 4) * 64 + (size_t)wi * 16) * 256;
    const float* xbase = x + base;
    float*       obase = out + base;

    const int wm = (wid & 3) * 16;
    const int wn = (wid >> 2) * 128;

    // ldmatrix lane->address components
    const int aRow  = ((lane >> 3) & 1) * 8 + (lane & 7);  // A-type / trans-B q-row
    const int aKblk = (lane >> 4) * 8;                     // A-type k add / trans-B j add
    const int bRow  = (lane >> 4) * 8 + (lane & 7);        // B-type (G1) j-row
    const int bKblk = ((lane >> 3) & 1) * 8;               // B-type (G1) k add

    // ---- prefetch Wp chunk 0 via cp.async (overlaps with LN) ----
    {
        const char* src = (const char*)(g_WpH + (size_t)tid * 256);
        const uint32_t dst = sb + OFF_B0 + tid * (WS * 2);
        #pragma unroll
        for (int q = 0; q < 8; ++q) cp16(dst + q * 16, src + q * 16);
        CP_COMMIT();
    }

    // ---- LayerNorm -> fp16 into sXh ----
    {
        const float4 ga0 = *(const float4*)(gamma + lane * 8);
        const float4 ga1 = *(const float4*)(gamma + lane * 8 + 4);
        const float4 bt0 = *(const float4*)(beta  + lane * 8);
        const float4 bt1 = *(const float4*)(beta  + lane * 8 + 4);
        #pragma unroll
        for (int tt = 0; tt < 8; ++tt) {
            const int t = wid * 8 + tt;
            const float* row = xbase + (((t >> 4) * 64 + (t & 15)) << 8);
            float4 v0 = *(const float4*)(row + lane * 8);
            float4 v1 = *(const float4*)(row + lane * 8 + 4);
            float s  = v0.x + v0.y + v0.z + v0.w + v1.x + v1.y + v1.z + v1.w;
            float s2 = v0.x*v0.x + v0.y*v0.y + v0.z*v0.z + v0.w*v0.w
                     + v1.x*v1.x + v1.y*v1.y + v1.z*v1.z + v1.w*v1.w;
            #pragma unroll
            for (int o = 16; o > 0; o >>= 1) {
                s  += __shfl_xor_sync(0xffffffffu, s,  o);
                s2 += __shfl_xor_sync(0xffffffffu, s2, o);
            }
            const float mu   = s * (1.0f / ED);
            const float var  = s2 * (1.0f / ED) - mu * mu;
            const float rstd = rsqrtf(var + 1e-5f);
            float nv[8];
            nv[0] = (v0.x - mu) * rstd * ga0.x + bt0.x;
            nv[1] = (v0.y - mu) * rstd * ga0.y + bt0.y;
            nv[2] = (v0.z - mu) * rstd * ga0.z + bt0.z;
            nv[3] = (v0.w - mu) * rstd * ga0.w + bt0.w;
            nv[4] = (v1.x - mu) * rstd * ga1.x + bt1.x;
            nv[5] = (v1.y - mu) * rstd * ga1.y + bt1.y;
            nv[6] = (v1.z - mu) * rstd * ga1.z + bt1.z;
            nv[7] = (v1.w - mu) * rstd * ga1.w + bt1.w;
            uint32_t hh[4];
            #pragma unroll
            for (int i2 = 0; i2 < 4; ++i2) {
                __half2 vh = __halves2half2(__float2half_rn(nv[2 * i2]),
                                            __float2half_rn(nv[2 * i2 + 1]));
                hh[i2] = *(uint32_t*)&vh;
            }
            *(uint4*)(smem + OFF_XH + t * (XS * 2) + lane * 16) =
                make_uint4(hh[0], hh[1], hh[2], hh[3]);
        }
    }
    CP_WAIT0();
    __syncthreads();                       // sync 1: xn + chunk0 visible

    // ---- GEMM1: y = xn @ Wp^T (fp16 HMMA), double-buffered chunks ----
    float acc[16][4];
    #pragma unroll
    for (int t = 0; t < 16; ++t)
        #pragma unroll
        for (int i2 = 0; i2 < 4; ++i2) acc[t][i2] = 0.0f;

    #pragma unroll
    for (int c = 0; c < 4; ++c) {
        if (c < 3) {
            // prefetch chunk c+1 into the other buffer
            const char* src = (const char*)(g_WpH + (size_t)tid * 256 + (c + 1) * KC);
            const uint32_t dst =
                sb + (((c + 1) & 1) ? OFF_B1 : OFF_B0) + tid * (WS * 2);
            #pragma unroll
            for (int q = 0; q < 8; ++q) cp16(dst + q * 16, src + q * 16);
        } else {
            // prefetch A_w into B0 during the last chunk's MMAs (B1 is live, B0 dead)
            const __half* srcA = g_AH + (size_t)w * 4096 + (tid >> 2) * 64 + (tid & 3) * 16;
            const uint32_t dstA = sb + OFF_A + (tid >> 2) * (AS * 2) + (tid & 3) * 32;
            cp16(dstA,      srcA);
            cp16(dstA + 16, srcA + 8);
        }
        CP_COMMIT();

        const uint32_t bufb = sb + ((c & 1) ? OFF_B1 : OFF_B0);
        #pragma unroll
        for (int ks = 0; ks < KC; ks += 16) {
            uint32_t aH[4];
            ldm4(aH, sb + OFF_XH + (wm + aRow) * (XS * 2) + (c * KC + ks + aKblk) * 2);
            #pragma unroll
            for (int g = 0; g < 8; ++g) {
                const int j0 = wn + g * 16;
                uint32_t bh[4];
                ldm4(bh, bufb + (j0 + bRow) * (WS * 2) + (ks + bKblk) * 2);
                mma16816(acc[2 * g],     aH, bh[0], bh[1]);
                mma16816(acc[2 * g + 1], aH, bh[2], bh[3]);
            }
        }
        CP_WAIT0();
        __syncthreads();                   // syncs 2-5
    }

    // ---- epilogue1: y = acc + bias -> fp16 into sXh (xn dead) ----
    #pragma unroll
    for (int t = 0; t < 16; ++t) {
        const int j = wn + t * 8 + 2 * tig;
        const float2 bb = *(const float2*)(bp + j);
        float y00 = acc[t][0] + bb.x, y01 = acc[t][1] + bb.y;   // row wm+gid
        float y10 = acc[t][2] + bb.x, y11 = acc[t][3] + bb.y;   // row wm+gid+8
        __half2 vh0 = __halves2half2(__float2half_rn(y00), __float2half_rn(y01));
        __half2 vh1 = __halves2half2(__float2half_rn(y10), __float2half_rn(y11));
        *(uint32_t*)(smem + OFF_XH + (wm + gid)     * (XS * 2) + j * 2) = *(uint32_t*)&vh0;
        *(uint32_t*)(smem + OFF_XH + (wm + gid + 8) * (XS * 2) + j * 2) = *(uint32_t*)&vh1;
    }
    __syncthreads();                       // sync 6: y + A_w visible

    // ---- GEMM2: z = A_w @ y (fp16), K = 64; B via ldmatrix.trans ----
    #pragma unroll
    for (int t = 0; t < 16; ++t)
        #pragma unroll
        for (int i2 = 0; i2 < 4; ++i2) acc[t][i2] = 0.0f;

    #pragma unroll
    for (int ks = 0; ks < 64; ks += 16) {
        uint32_t aH[4];
        ldm4(aH, sb + OFF_A + (wm + aRow) * (AS * 2) + (ks + aKblk) * 2);
        #pragma unroll
        for (int g = 0; g < 8; ++g) {
            const int j0 = wn + g * 16;
            const uint32_t qoff = (uint32_t)((ks + aRow) * (XS * 2) + (j0 + aKblk) * 2);
            uint32_t bh[4];
            ldm4t(bh, sb + OFF_XH + qoff);
            mma16816(acc[2 * g],     aH, bh[0], bh[1]);
            mma16816(acc[2 * g + 1], aH, bh[2], bh[3]);
        }
    }

    // ---- direct write-back: acc -> gmem (32B row segments = full sectors) ----
    {
        const int p0 = wm + gid, p1 = p0 + 8;
        float* o0 = obase + (((p0 >> 4) * 64 + (p0 & 15)) << 8);
        float* o1 = obase + (((p1 >> 4) * 64 + (p1 & 15)) << 8);
        #pragma unroll
        for (int t = 0; t < 16; ++t) {
            const int j = wn + t * 8 + 2 * tig;
            *(float2*)(o0 + j) = make_float2(acc[t][0], acc[t][1]);
            *(float2*)(o1 + j) = make_float2(acc[t][2], acc[t][3]);
        }
    }
}

// ---------------------------------------------------------------------------
extern "C" void kernel_launch(void* const* d_in, const int* in_sizes, int n_in,
                              void* d_out, int out_size)
{
    (void)in_sizes; (void)n_in; (void)out_size;
    const float* x     = (const float*)d_in[0];
    const float* gamma = (const float*)d_in[1];
    const float* beta  = (const float*)d_in[2];
    const float* Wp    = (const float*)d_in[3];
    const float* bp    = (const float*)d_in[4];
    const float* eb    = (const float*)d_in[5];
    const float* deg   = (const float*)d_in[6];
    float* out = (float*)d_out;

    cudaFuncSetAttribute(window_kernel,
                         cudaFuncAttributeMaxDynamicSharedMemorySize, SMEM_TOTAL);

    split_wp_kernel<<<256, TPB>>>(Wp);
    precompute_A_kernel<<<NWIN, TPB>>>(deg, eb);
    window_kernel<<<2048, TPB, SMEM_TOTAL>>>(x, gamma, beta, bp, out);
}

// round 16
// speedup vs baseline: 3.5582x; 1.0100x over previous
#include <cuda_runtime.h>
#include <cuda_fp16.h>
#include <cstdint>

static constexpr int L    = 64;
static constexpr int ED   = 256;
static constexpr int NWIN = 256;
static constexpr int TPB  = 256;
static constexpr int KC   = 64;      // k-chunk for Wp staging

// smem strides (elements)
static constexpr int XS = 264;       // fp16 stride for xn / y rows (528 B)
static constexpr int WS = 72;        // fp16 stride for Wp chunk rows (144 B, 16B-aligned)
static constexpr int AS = 72;        // fp16 stride for A_w rows (144 B)

// smem offsets (bytes)
static constexpr int OFF_XH = 0;                         // 64*528 = 33792
static constexpr int OFF_B0 = 33792;                     // chunk buf 0 (36864)
static constexpr int OFF_B1 = OFF_B0 + 256 * WS * 2;     // 70656
static constexpr int OFF_A  = OFF_B0;                    // A_w aliases B0 rows 0..63
static constexpr int SMEM_TOTAL = OFF_B1 + 256 * WS * 2; // 107520 -> 2 CTAs/SM

// Pre-converted fp16 operand images
__device__ __half g_WpH[256 * 256];
__device__ __half g_AH[NWIN * 64 * 64];

// ---------------------------------------------------------------- helpers
__device__ __forceinline__ uint32_t smem_u32(const void* p) {
    uint32_t a;
    asm("{ .reg .u64 t; cvta.to.shared.u64 t, %1; cvt.u32.u64 %0, t; }"
        : "=r"(a) : "l"(p));
    return a;
}
__device__ __forceinline__ void cp16(uint32_t s, const void* g) {
    asm volatile(
        "{ .reg .u64 gg; cvta.to.global.u64 gg, %1;"
        "  cp.async.cg.shared.global [%0], [gg], 16; }"
        :: "r"(s), "l"(g) : "memory");
}
#define CP_COMMIT() asm volatile("cp.async.commit_group;" ::: "memory")
#define CP_WAIT0()  asm volatile("cp.async.wait_group 0;" ::: "memory")

// Named group barrier with compile-time immediate ID (hardened vs register-ID path)
__device__ __forceinline__ void bar_group_imm(int grp) {
    if (grp == 0) asm volatile("bar.sync 1, 128;" ::: "memory");
    else          asm volatile("bar.sync 2, 128;" ::: "memory");
}
__device__ __forceinline__ void ldm4(uint32_t* r, uint32_t a) {
    asm volatile("ldmatrix.sync.aligned.m8n8.x4.shared.b16 {%0,%1,%2,%3}, [%4];"
                 : "=r"(r[0]), "=r"(r[1]), "=r"(r[2]), "=r"(r[3]) : "r"(a));
}
__device__ __forceinline__ void ldm4t(uint32_t* r, uint32_t a) {
    asm volatile("ldmatrix.sync.aligned.m8n8.x4.trans.shared.b16 {%0,%1,%2,%3}, [%4];"
                 : "=r"(r[0]), "=r"(r[1]), "=r"(r[2]), "=r"(r[3]) : "r"(a));
}
__device__ __forceinline__ void mma16816(float* d, const uint32_t* a,
                                         uint32_t b0, uint32_t b1) {
    asm volatile(
        "mma.sync.aligned.m16n8k16.row.col.f32.f16.f16.f32 "
        "{%0,%1,%2,%3}, {%4,%5,%6,%7}, {%8,%9}, {%0,%1,%2,%3};"
        : "+f"(d[0]), "+f"(d[1]), "+f"(d[2]), "+f"(d[3])
        : "r"(a[0]), "r"(a[1]), "r"(a[2]), "r"(a[3]), "r"(b0), "r"(b1));
}

// ---------------------------------------------------------------------------
// Merged prep: block w computes A_w = deg@eb -> fp16, AND converts 256
// elements of Wp -> fp16.
// ---------------------------------------------------------------------------
__global__ __launch_bounds__(TPB) void prep_kernel(
    const float* __restrict__ deg, const float* __restrict__ eb,
    const float* __restrict__ Wp)
{
    __shared__ float sD[L][L];
    __shared__ float sE[L][L + 1];
    const int w = blockIdx.x;

    {
        int idx = w * TPB + threadIdx.x;       // covers 65536
        g_WpH[idx] = __float2half_rn(Wp[idx]);
    }

    const float* dw = deg + (size_t)w * L * L;
    const float* ew = eb + (size_t)w * L * L;
    for (int i = threadIdx.x; i < L * L; i += TPB) {
        sD[i >> 6][i & 63] = dw[i];
        sE[i >> 6][i & 63] = ew[i];
    }
    __syncthreads();
    const int tp = threadIdx.x >> 4;
    const int tq = threadIdx.x & 15;
    float acc[4][4];
    #pragma unroll
    for (int i = 0; i < 4; ++i)
        #pragma unroll
        for (int j = 0; j < 4; ++j) acc[i][j] = 0.0f;
    #pragma unroll 8
    for (int k = 0; k < L; ++k) {
        float a0 = sD[tp * 4 + 0][k], a1 = sD[tp * 4 + 1][k];
        float a2 = sD[tp * 4 + 2][k], a3 = sD[tp * 4 + 3][k];
        float b0 = sE[k][tq * 4 + 0], b1 = sE[k][tq * 4 + 1];
        float b2 = sE[k][tq * 4 + 2], b3 = sE[k][tq * 4 + 3];
        acc[0][0] += a0 * b0; acc[0][1] += a0 * b1; acc[0][2] += a0 * b2; acc[0][3] += a0 * b3;
        acc[1][0] += a1 * b0; acc[1][1] += a1 * b1; acc[1][2] += a1 * b2; acc[1][3] += a1 * b3;
        acc[2][0] += a2 * b0; acc[2][1] += a2 * b1; acc[2][2] += a2 * b2; acc[2][3] += a2 * b3;
        acc[3][0] += a3 * b0; acc[3][1] += a3 * b1; acc[3][2] += a3 * b2; acc[3][3] += a3 * b3;
    }
    #pragma unroll
    for (int i = 0; i < 4; ++i)
        #pragma unroll
        for (int j = 0; j < 4; ++j) {
            int p = tp * 4 + i, q = tq * 4 + j;
            g_AH[(size_t)w * 4096 + p * 64 + q] = __float2half_rn(acc[i][j]);
        }
}

// ---------------------------------------------------------------------------
// Main kernel: one block per window, fp16 HMMA, cp.async double-buffered Wp,
// group-split barriers (immediate IDs), direct accumulator->gmem write-back.
// ---------------------------------------------------------------------------
__global__ __launch_bounds__(TPB, 2) void window_kernel(
    const float* __restrict__ x,
    const float* __restrict__ gamma,
    const float* __restrict__ beta,
    const float* __restrict__ bp,
    float* __restrict__ out)
{
    extern __shared__ char smem[];
    const uint32_t sb = smem_u32(smem);
    const int tid  = threadIdx.x;
    const int wid  = tid >> 5;
    const int lane = tid & 31;
    const int gid  = lane >> 2;       // 0..7
    const int tig  = lane & 3;        // 0..3
    const int grp  = wid >> 2;        // 0 or 1 (barrier group, = n-half)

    const int n  = blockIdx.x;
    const int wi = n & 3;
    const int fi = (n >> 2) & 63;
    const int b  = n >> 8;
    const int w  = fi * 4 + wi;
    const size_t base =
        (((size_t)b * 256 + (size_t)fi * 4) * 64 + (size_t)wi * 16) * 256;
    const float* xbase = x + base;
    float*       obase = out + base;

    const int wm = (wid & 3) * 16;
    const int wn = grp * 128;

    // ldmatrix lane->address components
    const int aRow  = ((lane >> 3) & 1) * 8 + (lane & 7);  // A-type / trans-B q-row
    const int aKblk = (lane >> 4) * 8;                     // A-type k add / trans-B j add
    const int bRow  = (lane >> 4) * 8 + (lane & 7);        // B-type (G1) j-row
    const int bKblk = ((lane >> 3) & 1) * 8;               // B-type (G1) k add

    // ---- prefetch Wp chunk 0 via cp.async (overlaps with LN) ----
    {
        const char* src = (const char*)(g_WpH + (size_t)tid * 256);
        const uint32_t dst = sb + OFF_B0 + tid * (WS * 2);
        #pragma unroll
        for (int q = 0; q < 8; ++q) cp16(dst + q * 16, src + q * 16);
        CP_COMMIT();
    }

    // ---- LayerNorm -> fp16 into sXh ----
    {
        const float4 ga0 = *(const float4*)(gamma + lane * 8);
        const float4 ga1 = *(const float4*)(gamma + lane * 8 + 4);
        const float4 bt0 = *(const float4*)(beta  + lane * 8);
        const float4 bt1 = *(const float4*)(beta  + lane * 8 + 4);
        #pragma unroll
        for (int tt = 0; tt < 8; ++tt) {
            const int t = wid * 8 + tt;
            const float* row = xbase + (((t >> 4) * 64 + (t & 15)) << 8);
            float4 v0 = *(const float4*)(row + lane * 8);
            float4 v1 = *(const float4*)(row + lane * 8 + 4);
            float s  = v0.x + v0.y + v0.z + v0.w + v1.x + v1.y + v1.z + v1.w;
            float s2 = v0.x*v0.x + v0.y*v0.y + v0.z*v0.z + v0.w*v0.w
                     + v1.x*v1.x + v1.y*v1.y + v1.z*v1.z + v1.w*v1.w;
            #pragma unroll
            for (int o = 16; o > 0; o >>= 1) {
                s  += __shfl_xor_sync(0xffffffffu, s,  o);
                s2 += __shfl_xor_sync(0xffffffffu, s2, o);
            }
            const float mu   = s * (1.0f / ED);
            const float var  = s2 * (1.0f / ED) - mu * mu;
            const float rstd = rsqrtf(var + 1e-5f);
            float nv[8];
            nv[0] = (v0.x - mu) * rstd * ga0.x + bt0.x;
            nv[1] = (v0.y - mu) * rstd * ga0.y + bt0.y;
            nv[2] = (v0.z - mu) * rstd * ga0.z + bt0.z;
            nv[3] = (v0.w - mu) * rstd * ga0.w + bt0.w;
            nv[4] = (v1.x - mu) * rstd * ga1.x + bt1.x;
            nv[5] = (v1.y - mu) * rstd * ga1.y + bt1.y;
            nv[6] = (v1.z - mu) * rstd * ga1.z + bt1.z;
            nv[7] = (v1.w - mu) * rstd * ga1.w + bt1.w;
            uint32_t hh[4];
            #pragma unroll
            for (int i2 = 0; i2 < 4; ++i2) {
                __half2 vh = __halves2half2(__float2half_rn(nv[2 * i2]),
                                            __float2half_rn(nv[2 * i2 + 1]));
                hh[i2] = *(uint32_t*)&vh;
            }
            *(uint4*)(smem + OFF_XH + t * (XS * 2) + lane * 16) =
                make_uint4(hh[0], hh[1], hh[2], hh[3]);
        }
    }
    CP_WAIT0();
    __syncthreads();                       // full 1: xn + chunk0 visible

    // ---- GEMM1: y = xn @ Wp^T (fp16 HMMA), double-buffered chunks ----
    float acc[16][4];
    #pragma unroll
    for (int t = 0; t < 16; ++t)
        #pragma unroll
        for (int i2 = 0; i2 < 4; ++i2) acc[t][i2] = 0.0f;

    #pragma unroll
    for (int c = 0; c < 4; ++c) {
        if (c < 3) {
            const char* src = (const char*)(g_WpH + (size_t)tid * 256 + (c + 1) * KC);
            const uint32_t dst =
                sb + (((c + 1) & 1) ? OFF_B1 : OFF_B0) + tid * (WS * 2);
            #pragma unroll
            for (int q = 0; q < 8; ++q) cp16(dst + q * 16, src + q * 16);
        } else if (tid < 128) {
            // group 0 only: A_w -> B0 rows 0..63 (disjoint from group 1's rows)
            const int r = tid >> 1, seg = tid & 1;
            const __half* srcA = g_AH + (size_t)w * 4096 + r * 64 + seg * 32;
            const uint32_t dstA = sb + OFF_A + r * (AS * 2) + seg * 64;
            cp16(dstA,      srcA);
            cp16(dstA + 16, srcA + 8);
            cp16(dstA + 32, srcA + 16);
            cp16(dstA + 48, srcA + 24);
        }
        CP_COMMIT();

        const uint32_t bufb = sb + ((c & 1) ? OFF_B1 : OFF_B0);
        #pragma unroll
        for (int ks = 0; ks < KC; ks += 16) {
            uint32_t aH[4];
            ldm4(aH, sb + OFF_XH + (wm + aRow) * (XS * 2) + (c * KC + ks + aKblk) * 2);
            #pragma unroll
            for (int g = 0; g < 8; ++g) {
                const int j0 = wn + g * 16;
                uint32_t bh[4];
                ldm4(bh, bufb + (j0 + bRow) * (WS * 2) + (ks + bKblk) * 2);
                mma16816(acc[2 * g],     aH, bh[0], bh[1]);
                mma16816(acc[2 * g + 1], aH, bh[2], bh[3]);
            }
        }
        CP_WAIT0();
        if (c < 3) bar_group_imm(grp);     // group barriers (imm ids 1,2)
        else       __syncthreads();        // full 2: all xn reads done
    }

    // ---- epilogue1: y = acc + bias -> fp16 into sXh (xn dead) ----
    #pragma unroll
    for (int t = 0; t < 16; ++t) {
        const int j = wn + t * 8 + 2 * tig;
        const float2 bb = *(const float2*)(bp + j);
        float y00 = acc[t][0] + bb.x, y01 = acc[t][1] + bb.y;   // row wm+gid
        float y10 = acc[t][2] + bb.x, y11 = acc[t][3] + bb.y;   // row wm+gid+8
        __half2 vh0 = __halves2half2(__float2half_rn(y00), __float2half_rn(y01));
        __half2 vh1 = __halves2half2(__float2half_rn(y10), __float2half_rn(y11));
        *(uint32_t*)(smem + OFF_XH + (wm + gid)     * (XS * 2) + j * 2) = *(uint32_t*)&vh0;
        *(uint32_t*)(smem + OFF_XH + (wm + gid + 8) * (XS * 2) + j * 2) = *(uint32_t*)&vh1;
    }
    __syncthreads();                       // full 3: y + A_w visible

    // ---- GEMM2: z = A_w @ y (fp16), K = 64; B via ldmatrix.trans ----
    #pragma unroll
    for (int t = 0; t < 16; ++t)
        #pragma unroll
        for (int i2 = 0; i2 < 4; ++i2) acc[t][i2] = 0.0f;

    #pragma unroll
    for (int ks = 0; ks < 64; ks += 16) {
        uint32_t aH[4];
        ldm4(aH, sb + OFF_A + (wm + aRow) * (AS * 2) + (ks + aKblk) * 2);
        #pragma unroll
        for (int g = 0; g < 8; ++g) {
            const int j0 = wn + g * 16;
            const uint32_t qoff = (uint32_t)((ks + aRow) * (XS * 2) + (j0 + aKblk) * 2);
            uint32_t bh[4];
            ldm4t(bh, sb + OFF_XH + qoff);
            mma16816(acc[2 * g],     aH, bh[0], bh[1]);
            mma16816(acc[2 * g + 1], aH, bh[2], bh[3]);
        }
    }

    // ---- direct write-back: acc -> gmem (32B row segments = full sectors) ----
    {
        const int p0 = wm + gid, p1 = p0 + 8;
        float* o0 = obase + (((p0 >> 4) * 64 + (p0 & 15)) << 8);
        float* o1 = obase + (((p1 >> 4) * 64 + (p1 & 15)) << 8);
        #pragma unroll
        for (int t = 0; t < 16; ++t) {
            const int j = wn + t * 8 + 2 * tig;
            *(float2*)(o0 + j) = make_float2(acc[t][0], acc[t][1]);
            *(float2*)(o1 + j) = make_float2(acc[t][2], acc[t][3]);
        }
    }
}

// ---------------------------------------------------------------------------
extern "C" void kernel_launch(void* const* d_in, const int* in_sizes, int n_in,
                              void* d_out, int out_size)
{
    (void)in_sizes; (void)n_in; (void)out_size;
    const float* x     = (const float*)d_in[0];
    const float* gamma = (const float*)d_in[1];
    const float* beta  = (const float*)d_in[2];
    const float* Wp    = (const float*)d_in[3];
    const float* bp    = (const float*)d_in[4];
    const float* eb    = (const float*)d_in[5];
    const float* deg   = (const float*)d_in[6];
    float* out = (float*)d_out;

    cudaFuncSetAttribute(window_kernel,
                         cudaFuncAttributeMaxDynamicSharedMemorySize, SMEM_TOTAL);

    prep_kernel<<<NWIN, TPB>>>(deg, eb, Wp);
    window_kernel<<<2048, TPB, SMEM_TOTAL>>>(x, gamma, beta, bp, out);
}

// round 17
// speedup vs baseline: 3.7525x; 1.0546x over previous
#include <cuda_runtime.h>
#include <cuda_fp16.h>
#include <cstdint>

static constexpr int L    = 64;
static constexpr int ED   = 256;
static constexpr int NWIN = 256;
static constexpr int TPB  = 256;
static constexpr int KC   = 64;      // k-chunk for Wp staging

// smem strides (elements)
static constexpr int XS = 264;       // fp16 stride for xn / y rows (528 B)
static constexpr int WS = 72;        // fp16 stride for Wp chunk rows (144 B, 16B-aligned)
static constexpr int AS = 72;        // fp16 stride for A_w rows (144 B)

// smem offsets (bytes)
static constexpr int OFF_XH = 0;                         // 64*528 = 33792
static constexpr int OFF_B0 = 33792;                     // chunk buf 0 (36864)
static constexpr int OFF_B1 = OFF_B0 + 256 * WS * 2;     // 70656
static constexpr int OFF_A  = OFF_B0;                    // A_w aliases B0 rows 0..63
static constexpr int SMEM_TOTAL = OFF_B1 + 256 * WS * 2; // 107520 -> 2 CTAs/SM

// Pre-converted fp16 operand images
__device__ __half g_WpH[256 * 256];
__device__ __half g_AH[NWIN * 64 * 64];

// ---------------------------------------------------------------- helpers
__device__ __forceinline__ uint32_t smem_u32(const void* p) {
    uint32_t a;
    asm("{ .reg .u64 t; cvta.to.shared.u64 t, %1; cvt.u32.u64 %0, t; }"
        : "=r"(a) : "l"(p));
    return a;
}
__device__ __forceinline__ void cp16(uint32_t s, const void* g) {
    asm volatile(
        "{ .reg .u64 gg; cvta.to.global.u64 gg, %1;"
        "  cp.async.cg.shared.global [%0], [gg], 16; }"
        :: "r"(s), "l"(g) : "memory");
}
#define CP_COMMIT() asm volatile("cp.async.commit_group;" ::: "memory")
#define CP_WAIT0()  asm volatile("cp.async.wait_group 0;" ::: "memory")

// Named group barrier with compile-time immediate ID
__device__ __forceinline__ void bar_group_imm(int grp) {
    if (grp == 0) asm volatile("bar.sync 1, 128;" ::: "memory");
    else          asm volatile("bar.sync 2, 128;" ::: "memory");
}
__device__ __forceinline__ void ldm4(uint32_t* r, uint32_t a) {
    asm volatile("ldmatrix.sync.aligned.m8n8.x4.shared.b16 {%0,%1,%2,%3}, [%4];"
                 : "=r"(r[0]), "=r"(r[1]), "=r"(r[2]), "=r"(r[3]) : "r"(a));
}
__device__ __forceinline__ void ldm4t(uint32_t* r, uint32_t a) {
    asm volatile("ldmatrix.sync.aligned.m8n8.x4.trans.shared.b16 {%0,%1,%2,%3}, [%4];"
                 : "=r"(r[0]), "=r"(r[1]), "=r"(r[2]), "=r"(r[3]) : "r"(a));
}
__device__ __forceinline__ void mma16816(float* d, const uint32_t* a,
                                         uint32_t b0, uint32_t b1) {
    asm volatile(
        "mma.sync.aligned.m16n8k16.row.col.f32.f16.f16.f32 "
        "{%0,%1,%2,%3}, {%4,%5,%6,%7}, {%8,%9}, {%0,%1,%2,%3};"
        : "+f"(d[0]), "+f"(d[1]), "+f"(d[2]), "+f"(d[3])
        : "r"(a[0]), "r"(a[1]), "r"(a[2]), "r"(a[3]), "r"(b0), "r"(b1));
}

// ---------------------------------------------------------------------------
// Merged prep: block w computes A_w = deg@eb -> fp16 AND converts 256 Wp elems.
// ---------------------------------------------------------------------------
__global__ __launch_bounds__(TPB) void prep_kernel(
    const float* __restrict__ deg, const float* __restrict__ eb,
    const float* __restrict__ Wp)
{
    __shared__ float sD[L][L];
    __shared__ float sE[L][L + 1];
    const int w = blockIdx.x;

    {
        int idx = w * TPB + threadIdx.x;       // covers 65536
        g_WpH[idx] = __float2half_rn(Wp[idx]);
    }

    const float* dw = deg + (size_t)w * L * L;
    const float* ew = eb + (size_t)w * L * L;
    for (int i = threadIdx.x; i < L * L; i += TPB) {
        sD[i >> 6][i & 63] = dw[i];
        sE[i >> 6][i & 63] = ew[i];
    }
    __syncthreads();
    const int tp = threadIdx.x >> 4;
    const int tq = threadIdx.x & 15;
    float acc[4][4];
    #pragma unroll
    for (int i = 0; i < 4; ++i)
        #pragma unroll
        for (int j = 0; j < 4; ++j) acc[i][j] = 0.0f;
    #pragma unroll 8
    for (int k = 0; k < L; ++k) {
        float a0 = sD[tp * 4 + 0][k], a1 = sD[tp * 4 + 1][k];
        float a2 = sD[tp * 4 + 2][k], a3 = sD[tp * 4 + 3][k];
        float b0 = sE[k][tq * 4 + 0], b1 = sE[k][tq * 4 + 1];
        float b2 = sE[k][tq * 4 + 2], b3 = sE[k][tq * 4 + 3];
        acc[0][0] += a0 * b0; acc[0][1] += a0 * b1; acc[0][2] += a0 * b2; acc[0][3] += a0 * b3;
        acc[1][0] += a1 * b0; acc[1][1] += a1 * b1; acc[1][2] += a1 * b2; acc[1][3] += a1 * b3;
        acc[2][0] += a2 * b0; acc[2][1] += a2 * b1; acc[2][2] += a2 * b2; acc[2][3] += a2 * b3;
        acc[3][0] += a3 * b0; acc[3][1] += a3 * b1; acc[3][2] += a3 * b2; acc[3][3] += a3 * b3;
    }
    #pragma unroll
    for (int i = 0; i < 4; ++i)
        #pragma unroll
        for (int j = 0; j < 4; ++j) {
            int p = tp * 4 + i, q = tq * 4 + j;
            g_AH[(size_t)w * 4096 + p * 64 + q] = __float2half_rn(acc[i][j]);
        }
}

// ---------------------------------------------------------------------------
// Main kernel: one block per window, fp16 HMMA, cp.async double-buffered Wp.
// Warp tile = 32m x 64n: wm = (wid&1)*32, wn = ((wid>>1)&1)*64 + grp*128.
// Per k-step: 2 A-frags + 4 B-frags (6 LDSM) for 16 MMAs.
// ---------------------------------------------------------------------------
__global__ __launch_bounds__(TPB, 2) void window_kernel(
    const float* __restrict__ x,
    const float* __restrict__ gamma,
    const float* __restrict__ beta,
    const float* __restrict__ bp,
    float* __restrict__ out)
{
    extern __shared__ char smem[];
    const uint32_t sb = smem_u32(smem);
    const int tid  = threadIdx.x;
    const int wid  = tid >> 5;
    const int lane = tid & 31;
    const int gid  = lane >> 2;       // 0..7
    const int tig  = lane & 3;        // 0..3
    const int grp  = wid >> 2;        // 0 or 1 (barrier group = Wp n-half)

    const int n  = blockIdx.x;
    const int wi = n & 3;
    const int fi = (n >> 2) & 63;
    const int b  = n >> 8;
    const int w  = fi * 4 + wi;
    const size_t base =
        (((size_t)b * 256 + (size_t)fi * 4) * 64 + (size_t)wi * 16) * 256;
    const float* xbase = x + base;
    float*       obase = out + base;

    const int wm = (wid & 1) * 32;                       // m-rows wm..wm+31
    const int wn = ((wid >> 1) & 1) * 64 + grp * 128;    // n-cols wn..wn+63

    // ldmatrix lane->address components
    const int aRow  = ((lane >> 3) & 1) * 8 + (lane & 7);  // A-type / trans-B q-row
    const int aKblk = (lane >> 4) * 8;                     // A-type k add / trans-B j add
    const int bRow  = (lane >> 4) * 8 + (lane & 7);        // B-type (G1) j-row
    const int bKblk = ((lane >> 3) & 1) * 8;               // B-type (G1) k add

    // ---- prefetch Wp chunk 0 via cp.async (overlaps with LN) ----
    {
        const char* src = (const char*)(g_WpH + (size_t)tid * 256);
        const uint32_t dst = sb + OFF_B0 + tid * (WS * 2);
        #pragma unroll
        for (int q = 0; q < 8; ++q) cp16(dst + q * 16, src + q * 16);
        CP_COMMIT();
    }

    // ---- LayerNorm -> fp16 into sXh ----
    {
        const float4 ga0 = *(const float4*)(gamma + lane * 8);
        const float4 ga1 = *(const float4*)(gamma + lane * 8 + 4);
        const float4 bt0 = *(const float4*)(beta  + lane * 8);
        const float4 bt1 = *(const float4*)(beta  + lane * 8 + 4);
        #pragma unroll
        for (int tt = 0; tt < 8; ++tt) {
            const int t = wid * 8 + tt;
            const float* row = xbase + (((t >> 4) * 64 + (t & 15)) << 8);
            float4 v0 = *(const float4*)(row + lane * 8);
            float4 v1 = *(const float4*)(row + lane * 8 + 4);
            float s  = v0.x + v0.y + v0.z + v0.w + v1.x + v1.y + v1.z + v1.w;
            float s2 = v0.x*v0.x + v0.y*v0.y + v0.z*v0.z + v0.w*v0.w
                     + v1.x*v1.x + v1.y*v1.y + v1.z*v1.z + v1.w*v1.w;
            #pragma unroll
            for (int o = 16; o > 0; o >>= 1) {
                s  += __shfl_xor_sync(0xffffffffu, s,  o);
                s2 += __shfl_xor_sync(0xffffffffu, s2, o);
            }
            const float mu   = s * (1.0f / ED);
            const float var  = s2 * (1.0f / ED) - mu * mu;
            const float rstd = rsqrtf(var + 1e-5f);
            float nv[8];
            nv[0] = (v0.x - mu) * rstd * ga0.x + bt0.x;
            nv[1] = (v0.y - mu) * rstd * ga0.y + bt0.y;
            nv[2] = (v0.z - mu) * rstd * ga0.z + bt0.z;
            nv[3] = (v0.w - mu) * rstd * ga0.w + bt0.w;
            nv[4] = (v1.x - mu) * rstd * ga1.x + bt1.x;
            nv[5] = (v1.y - mu) * rstd * ga1.y + bt1.y;
            nv[6] = (v1.z - mu) * rstd * ga1.z + bt1.z;
            nv[7] = (v1.w - mu) * rstd * ga1.w + bt1.w;
            uint32_t hh[4];
            #pragma unroll
            for (int i2 = 0; i2 < 4; ++i2) {
                __half2 vh = __halves2half2(__float2half_rn(nv[2 * i2]),
                                            __float2half_rn(nv[2 * i2 + 1]));
                hh[i2] = *(uint32_t*)&vh;
            }
            *(uint4*)(smem + OFF_XH + t * (XS * 2) + lane * 16) =
                make_uint4(hh[0], hh[1], hh[2], hh[3]);
        }
    }
    CP_WAIT0();
    __syncthreads();                       // full 1: xn + chunk0 visible

    // ---- GEMM1: y = xn @ Wp^T (fp16 HMMA), double-buffered chunks ----
    float acc0[8][4], acc1[8][4];          // m-subtile 0 (wm..+15), 1 (wm+16..+31)
    #pragma unroll
    for (int t = 0; t < 8; ++t)
        #pragma unroll
        for (int i2 = 0; i2 < 4; ++i2) { acc0[t][i2] = 0.0f; acc1[t][i2] = 0.0f; }

    #pragma unroll
    for (int c = 0; c < 4; ++c) {
        if (c < 3) {
            const char* src = (const char*)(g_WpH + (size_t)tid * 256 + (c + 1) * KC);
            const uint32_t dst =
                sb + (((c + 1) & 1) ? OFF_B1 : OFF_B0) + tid * (WS * 2);
            #pragma unroll
            for (int q = 0; q < 8; ++q) cp16(dst + q * 16, src + q * 16);
        } else if (tid < 128) {
            // group 0 only: A_w -> B0 rows 0..63 (disjoint from group 1's rows)
            const int r = tid >> 1, seg = tid & 1;
            const __half* srcA = g_AH + (size_t)w * 4096 + r * 64 + seg * 32;
            const uint32_t dstA = sb + OFF_A + r * (AS * 2) + seg * 64;
            cp16(dstA,      srcA);
            cp16(dstA + 16, srcA + 8);
            cp16(dstA + 32, srcA + 16);
            cp16(dstA + 48, srcA + 24);
        }
        CP_COMMIT();

        const uint32_t bufb = sb + ((c & 1) ? OFF_B1 : OFF_B0);
        #pragma unroll
        for (int ks = 0; ks < KC; ks += 16) {
            uint32_t aH0[4], aH1[4];
            ldm4(aH0, sb + OFF_XH + (wm + aRow)      * (XS * 2) + (c * KC + ks + aKblk) * 2);
            ldm4(aH1, sb + OFF_XH + (wm + 16 + aRow) * (XS * 2) + (c * KC + ks + aKblk) * 2);
            uint32_t bh[4][4];
            #pragma unroll
            for (int g = 0; g < 4; ++g)
                ldm4(bh[g], bufb + (wn + g * 16 + bRow) * (WS * 2) + (ks + bKblk) * 2);
            #pragma unroll
            for (int g = 0; g < 4; ++g) {
                mma16816(acc0[2 * g],     aH0, bh[g][0], bh[g][1]);
                mma16816(acc0[2 * g + 1], aH0, bh[g][2], bh[g][3]);
                mma16816(acc1[2 * g],     aH1, bh[g][0], bh[g][1]);
                mma16816(acc1[2 * g + 1], aH1, bh[g][2], bh[g][3]);
            }
        }
        CP_WAIT0();
        if (c < 3) bar_group_imm(grp);     // group barriers (imm ids 1,2)
        else       __syncthreads();        // full 2: all xn reads done
    }

    // ---- epilogue1: y = acc + bias -> fp16 into sXh (xn dead) ----
    #pragma unroll
    for (int t = 0; t < 8; ++t) {
        const int j = wn + t * 8 + 2 * tig;
        const float2 bb = *(const float2*)(bp + j);
        // rows wm+gid, wm+gid+8 from acc0; wm+16+gid, wm+24+gid from acc1
        __half2 v00 = __halves2half2(__float2half_rn(acc0[t][0] + bb.x),
                                     __float2half_rn(acc0[t][1] + bb.y));
        __half2 v01 = __halves2half2(__float2half_rn(acc0[t][2] + bb.x),
                                     __float2half_rn(acc0[t][3] + bb.y));
        __half2 v10 = __halves2half2(__float2half_rn(acc1[t][0] + bb.x),
                                     __float2half_rn(acc1[t][1] + bb.y));
        __half2 v11 = __halves2half2(__float2half_rn(acc1[t][2] + bb.x),
                                     __float2half_rn(acc1[t][3] + bb.y));
        *(uint32_t*)(smem + OFF_XH + (wm + gid)      * (XS * 2) + j * 2) = *(uint32_t*)&v00;
        *(uint32_t*)(smem + OFF_XH + (wm + gid + 8)  * (XS * 2) + j * 2) = *(uint32_t*)&v01;
        *(uint32_t*)(smem + OFF_XH + (wm + 16 + gid) * (XS * 2) + j * 2) = *(uint32_t*)&v10;
        *(uint32_t*)(smem + OFF_XH + (wm + 24 + gid) * (XS * 2) + j * 2) = *(uint32_t*)&v11;
    }
    __syncthreads();                       // full 3: y + A_w visible

    // ---- GEMM2: z = A_w @ y (fp16), K = 64; B via ldmatrix.trans ----
    #pragma unroll
    for (int t = 0; t < 8; ++t)
        #pragma unroll
        for (int i2 = 0; i2 < 4; ++i2) { acc0[t][i2] = 0.0f; acc1[t][i2] = 0.0f; }

    #pragma unroll
    for (int ks = 0; ks < 64; ks += 16) {
        uint32_t aH0[4], aH1[4];
        ldm4(aH0, sb + OFF_A + (wm + aRow)      * (AS * 2) + (ks + aKblk) * 2);
        ldm4(aH1, sb + OFF_A + (wm + 16 + aRow) * (AS * 2) + (ks + aKblk) * 2);
        uint32_t bh[4][4];
        #pragma unroll
        for (int g = 0; g < 4; ++g) {
            // trans tiles: q = ks + aRow, j = wn + g*16 + aKblk
            const uint32_t qoff =
                (uint32_t)((ks + aRow) * (XS * 2) + (wn + g * 16 + aKblk) * 2);
            ldm4t(bh[g], sb + OFF_XH + qoff);
        }
        #pragma unroll
        for (int g = 0; g < 4; ++g) {
            mma16816(acc0[2 * g],     aH0, bh[g][0], bh[g][1]);
            mma16816(acc0[2 * g + 1], aH0, bh[g][2], bh[g][3]);
            mma16816(acc1[2 * g],     aH1, bh[g][0], bh[g][1]);
            mma16816(acc1[2 * g + 1], aH1, bh[g][2], bh[g][3]);
        }
    }

    // ---- direct write-back: acc -> gmem (32B row segments = full sectors) ----
    {
        const int p0 = wm + gid,      p1 = p0 + 8;
        const int p2 = wm + 16 + gid, p3 = p2 + 8;
        float* o0 = obase + (((p0 >> 4) * 64 + (p0 & 15)) << 8);
        float* o1 = obase + (((p1 >> 4) * 64 + (p1 & 15)) << 8);
        float* o2 = obase + (((p2 >> 4) * 64 + (p2 & 15)) << 8);
        float* o3 = obase + (((p3 >> 4) * 64 + (p3 & 15)) << 8);
        #pragma unroll
        for (int t = 0; t < 8; ++t) {
            const int j = wn + t * 8 + 2 * tig;
            *(float2*)(o0 + j) = make_float2(acc0[t][0], acc0[t][1]);
            *(float2*)(o1 + j) = make_float2(acc0[t][2], acc0[t][3]);
            *(float2*)(o2 + j) = make_float2(acc1[t][0], acc1[t][1]);
            *(float2*)(o3 + j) = make_float2(acc1[t][2], acc1[t][3]);
        }
    }
}

// ---------------------------------------------------------------------------
extern "C" void kernel_launch(void* const* d_in, const int* in_sizes, int n_in,
                              void* d_out, int out_size)
{
    (void)in_sizes; (void)n_in; (void)out_size;
    const float* x     = (const float*)d_in[0];
    const float* gamma = (const float*)d_in[1];
    const float* beta  = (const float*)d_in[2];
    const float* Wp    = (const float*)d_in[3];
    const float* bp    = (const float*)d_in[4];
    const float* eb    = (const float*)d_in[5];
    const float* deg   = (const float*)d_in[6];
    float* out = (float*)d_out;

    cudaFuncSetAttribute(window_kernel,
                         cudaFuncAttributeMaxDynamicSharedMemorySize, SMEM_TOTAL);

    prep_kernel<<<NWIN, TPB>>>(deg, eb, Wp);
    window_kernel<<<2048, TPB, SMEM_TOTAL>>>(x, gamma, beta, bp, out);
}